// round 10
// baseline (speedup 1.0000x reference)
#include <cuda_runtime.h>
#include <cuda_bf16.h>
#include <cstdint>

// Problem constants
#define BATCH  2
#define T_SEQ  2048
#define WID    1024
#define HEADS  16
#define CH     64
#define W3     3072
#define MROWS  (BATCH * T_SEQ)   // 4096
#define BH_N   (BATCH * HEADS)   // 32

// Scratch (allocation-free rule: use __device__ globals)
__device__ float g_qkv [BATCH * T_SEQ * W3];    // 48 MB
__device__ float g_attn[BATCH * T_SEQ * WID];   // 16 MB
__device__ float g_kmean[BATCH * HEADS * CH];
__device__ float g_pos [BATCH * T_SEQ];
__device__ float g_aw  [BATCH * T_SEQ];

// Pre-split bf16 hi/lo operands for flash (written once by convert_kernel):
// Q/K: [bh][t][32 u32]  (channel-pair words; Q prescaled by 1/8)
// V:   [bh][t/2][64 u32] (key-pair words per channel)
#define QK_WORDS ((size_t)BH_N * T_SEQ * 32)   // 2M u32 = 8 MB each
__device__ uint32_t g_QH[QK_WORDS], g_QL[QK_WORDS];
__device__ uint32_t g_KH[QK_WORDS], g_KL[QK_WORDS];
__device__ uint32_t g_VH[QK_WORDS], g_VL[QK_WORDS];

// ---------------------------------------------------------------------------
// mma.sync helpers (plain PTX — legal in compute_103 PTX)
// ---------------------------------------------------------------------------
__device__ __forceinline__ void mma_bf16(float* c, const uint32_t* a, const uint32_t* b)
{
    asm volatile(
        "mma.sync.aligned.m16n8k16.row.col.f32.bf16.bf16.f32 "
        "{%0,%1,%2,%3}, {%4,%5,%6,%7}, {%8,%9}, {%0,%1,%2,%3};"
        : "+f"(c[0]), "+f"(c[1]), "+f"(c[2]), "+f"(c[3])
        : "r"(a[0]), "r"(a[1]), "r"(a[2]), "r"(a[3]),
          "r"(b[0]), "r"(b[1]));
}

// Split two fp32 into packed bf16x2 hi + lo words (low half = first value).
__device__ __forceinline__ void bsplit2(float x0, float x1,
                                        uint32_t& hi, uint32_t& lo)
{
    __nv_bfloat16 h0 = __float2bfloat16(x0);
    __nv_bfloat16 h1 = __float2bfloat16(x1);
    float f0 = __bfloat162float(h0), f1 = __bfloat162float(h1);
    __nv_bfloat16 l0 = __float2bfloat16(x0 - f0);
    __nv_bfloat16 l1 = __float2bfloat16(x1 - f1);
    hi = (uint32_t)__bfloat16_as_ushort(h0) |
         ((uint32_t)__bfloat16_as_ushort(h1) << 16);
    lo = (uint32_t)__bfloat16_as_ushort(l0) |
         ((uint32_t)__bfloat16_as_ushort(l1) << 16);
}

// u32-packed A-frag (m16k16 bf16). lane = gid*4+tig; kw = k-word offset (k/2).
__device__ __forceinline__ void frag_au(uint32_t* a, const uint32_t* S, int SA,
                                        int r, int kw, int gid, int tig)
{
    const uint32_t* p0 = S + (r + gid) * SA + kw + tig;
    const uint32_t* p1 = S + (r + gid + 8) * SA + kw + tig;
    a[0] = p0[0]; a[1] = p1[0]; a[2] = p0[4]; a[3] = p1[4];
}

// ---------------------------------------------------------------------------
// Tensor-core GEMM, bf16x3 on m16n8k16 — validated R7/R9 version, unchanged.
// ---------------------------------------------------------------------------
static constexpr int BA_S = 20;    // A u32 row stride (16 words + pad)
static constexpr int BB_S = 136;   // B u32 kp-row stride (128 words + pad)
static constexpr int GB_AH = 0;
static constexpr int GB_AL = 128 * BA_S;             // 2560
static constexpr int GB_BH = 2 * 128 * BA_S;         // 5120
static constexpr int GB_BL = GB_BH + 16 * BB_S;      // 7296
static constexpr int G_TOT = (GB_BL + 16 * BB_S) * 4; // 37888 bytes

__global__ __launch_bounds__(256) void gemm_bf16(
    const float* __restrict__ A, const float* __restrict__ B,
    const float* __restrict__ bias, float* __restrict__ C,
    int N, int K)
{
    extern __shared__ uint32_t smu[];
    uint32_t* AH = smu + GB_AH;
    uint32_t* AL = smu + GB_AL;
    uint32_t* BH = smu + GB_BH;
    uint32_t* BL = smu + GB_BL;

    const int tid = threadIdx.x;
    const int wid = tid >> 5;
    const int lane = tid & 31;
    const int gid = lane >> 2, tig = lane & 3;
    const int wm = (wid >> 1) * 32;   // warp row offset in tile
    const int wn = (wid & 1) * 64;    // warp col offset in tile
    const int row0 = blockIdx.y * 128;
    const int col0 = blockIdx.x * 128;

    // stagers
    const int ar  = tid >> 1;           // 0..127
    const int ak  = (tid & 1) * 16;     // float offset 0 or 16
    const int bkp = tid >> 4;           // 0..15 (k-pair row)
    const int bn0 = (tid & 15) * 8;     // 0..120

    const float* Ap  = A + (size_t)(row0 + ar) * K + ak;
    const float* Bp0 = B + col0 + bn0;

    float c[2][8][4];
    #pragma unroll
    for (int i = 0; i < 2; i++)
        #pragma unroll
        for (int j = 0; j < 8; j++)
            #pragma unroll
            for (int q = 0; q < 4; q++) c[i][j][q] = 0.f;

    for (int kc = 0; kc < K; kc += 32) {
        __syncthreads();
        // ---- stage A (128 x 32 fp32 -> 128 x 16 u32 hi/lo) ----
        #pragma unroll
        for (int i = 0; i < 4; i++) {
            float4 v = *(const float4*)(Ap + kc + i * 4);
            uint32_t h0, l0, h1, l1;
            bsplit2(v.x, v.y, h0, l0);
            bsplit2(v.z, v.w, h1, l1);
            const int w = ar * BA_S + ak / 2 + i * 2;
            AH[w] = h0; AH[w + 1] = h1;
            AL[w] = l0; AL[w + 1] = l1;
        }
        // ---- stage B (32 x 128 fp32 -> 16 kp-rows x 128 u32 hi/lo) ----
        {
            const float* Bp = Bp0 + (size_t)(kc + 2 * bkp) * N;
            float4 x0 = *(const float4*)(Bp);
            float4 x1 = *(const float4*)(Bp + 4);
            float4 y0 = *(const float4*)(Bp + N);
            float4 y1 = *(const float4*)(Bp + N + 4);
            const float xa[8] = {x0.x, x0.y, x0.z, x0.w, x1.x, x1.y, x1.z, x1.w};
            const float ya[8] = {y0.x, y0.y, y0.z, y0.w, y1.x, y1.y, y1.z, y1.w};
            #pragma unroll
            for (int cI = 0; cI < 8; cI++) {
                uint32_t hi, lo;
                bsplit2(xa[cI], ya[cI], hi, lo);   // word = (B[k][n], B[k+1][n])
                BH[bkp * BB_S + bn0 + cI] = hi;
                BL[bkp * BB_S + bn0 + cI] = lo;
            }
        }
        __syncthreads();

        // ---- MMA: 2 x k16 steps, bf16x3 ----
        #pragma unroll
        for (int ks = 0; ks < 2; ks++) {
            uint32_t ah[2][4], al_[2][4];
            frag_au(ah[0],  AH, BA_S, wm,      ks * 8, gid, tig);
            frag_au(ah[1],  AH, BA_S, wm + 16, ks * 8, gid, tig);
            frag_au(al_[0], AL, BA_S, wm,      ks * 8, gid, tig);
            frag_au(al_[1], AL, BA_S, wm + 16, ks * 8, gid, tig);
            #pragma unroll
            for (int j = 0; j < 8; j++) {
                const int base = (ks * 8 + tig) * BB_S + wn + j * 8 + gid;
                uint32_t bh[2], bl[2];
                bh[0] = BH[base]; bh[1] = BH[base + 4 * BB_S];
                bl[0] = BL[base]; bl[1] = BL[base + 4 * BB_S];
                #pragma unroll
                for (int i = 0; i < 2; i++) {
                    mma_bf16(c[i][j], ah[i],  bh);
                    mma_bf16(c[i][j], ah[i],  bl);
                    mma_bf16(c[i][j], al_[i], bh);
                }
            }
        }
    }

    // ---- epilogue: c frags + bias -> gmem ----
    #pragma unroll
    for (int i = 0; i < 2; i++) {
        const int r0 = row0 + wm + i * 16 + gid;
        #pragma unroll
        for (int j = 0; j < 8; j++) {
            const int col = col0 + wn + j * 8 + 2 * tig;
            float2 bv = *(const float2*)&bias[col];
            float2 o0 = make_float2(c[i][j][0] + bv.x, c[i][j][1] + bv.y);
            float2 o1 = make_float2(c[i][j][2] + bv.x, c[i][j][3] + bv.y);
            *(float2*)&C[(size_t)r0 * N + col]       = o0;
            *(float2*)&C[(size_t)(r0 + 8) * N + col] = o1;
        }
    }
}

// ---------------------------------------------------------------------------
// Convert: split Q (prescaled 1/8), K, V from fp32 g_qkv into packed bf16
// hi/lo arrays, in EXACTLY the layouts flash stages into smem. Done once,
// instead of 16x redundantly inside the flash grid.
// grid = (T/64, B*H), 256 threads.
// ---------------------------------------------------------------------------
__global__ __launch_bounds__(256) void convert_kernel()
{
    const int tid = threadIdx.x;
    const int bh  = blockIdx.y;
    const int b = bh >> 4, h = bh & 15;
    const int t0 = blockIdx.x * 64;
    const float* base = g_qkv + (size_t)b * T_SEQ * W3 + h * 192;

    // Q and K: r = tid>>2 (0..63), c0 = (tid&3)*16
    {
        const int r = tid >> 2, c0 = (tid & 3) * 16;
        const float* qrow = base + (size_t)(t0 + r) * W3 + c0;
        const float* krow = qrow + CH;
        const size_t g = ((size_t)bh * T_SEQ + t0 + r) * 32 + c0 / 2;
        #pragma unroll
        for (int i = 0; i < 4; i++) {
            float4 q = *(const float4*)(qrow + i * 4);
            uint32_t h0, l0, h1, l1;
            bsplit2(q.x * 0.125f, q.y * 0.125f, h0, l0);
            bsplit2(q.z * 0.125f, q.w * 0.125f, h1, l1);
            g_QH[g + i * 2] = h0; g_QH[g + i * 2 + 1] = h1;
            g_QL[g + i * 2] = l0; g_QL[g + i * 2 + 1] = l1;
            float4 k = *(const float4*)(krow + i * 4);
            bsplit2(k.x, k.y, h0, l0);
            bsplit2(k.z, k.w, h1, l1);
            g_KH[g + i * 2] = h0; g_KH[g + i * 2 + 1] = h1;
            g_KL[g + i * 2] = l0; g_KL[g + i * 2 + 1] = l1;
        }
    }
    // V: kp = tid>>3 (0..31), c0 = (tid&7)*8; word = (V[2kp][c], V[2kp+1][c])
    {
        const int kp = tid >> 3, c0 = (tid & 7) * 8;
        const float* v0 = base + (size_t)(t0 + 2 * kp) * W3 + 2 * CH + c0;
        const float* v1 = v0 + W3;
        float4 a0 = *(const float4*)(v0);
        float4 a1 = *(const float4*)(v0 + 4);
        float4 b0 = *(const float4*)(v1);
        float4 b1 = *(const float4*)(v1 + 4);
        const float va[8] = {a0.x, a0.y, a0.z, a0.w, a1.x, a1.y, a1.z, a1.w};
        const float vb[8] = {b0.x, b0.y, b0.z, b0.w, b1.x, b1.y, b1.z, b1.w};
        const size_t g = ((size_t)bh * (T_SEQ / 2) + t0 / 2 + kp) * 64 + c0;
        #pragma unroll
        for (int c = 0; c < 8; c++) {
            uint32_t hi, lo;
            bsplit2(va[c], vb[c], hi, lo);
            g_VH[g + c] = hi;
            g_VL[g + c] = lo;
        }
    }
}

// ---------------------------------------------------------------------------
// k_mean / pos / aw — unchanged
// ---------------------------------------------------------------------------
__global__ __launch_bounds__(256) void kmean_kernel()
{
    const int bh = blockIdx.x;
    const int b = bh >> 4, h = bh & 15;
    const int c  = threadIdx.x & 63;
    const int tg = threadIdx.x >> 6;
    const float* base = g_qkv + (size_t)b * T_SEQ * W3 + h * 192 + CH + c;
    float s = 0.f;
    for (int t = tg; t < T_SEQ; t += 4) s += base[(size_t)t * W3];
    __shared__ float red[4][64];
    red[tg][c] = s;
    __syncthreads();
    if (tg == 0) {
        float tot = red[0][c] + red[1][c] + red[2][c] + red[3][c];
        g_kmean[bh * CH + c] = tot * (1.f / (float)T_SEQ);
    }
}

__global__ __launch_bounds__(256) void pos_kernel()
{
    const int bt = blockIdx.x;
    const int b  = bt >> 11;
    const float* qb = g_qkv + (size_t)bt * W3;
    const float* km = g_kmean + b * WID;
    float s = 0.f;
    for (int j = threadIdx.x; j < WID; j += 256) {
        const int h = j >> 6, c = j & 63;
        s += qb[h * 192 + c] * km[j];
    }
    #pragma unroll
    for (int msk = 16; msk; msk >>= 1) s += __shfl_xor_sync(0xffffffffu, s, msk);
    __shared__ float red[8];
    if ((threadIdx.x & 31) == 0) red[threadIdx.x >> 5] = s;
    __syncthreads();
    if (threadIdx.x == 0) {
        float t = 0.f;
        #pragma unroll
        for (int w = 0; w < 8; w++) t += red[w];
        g_pos[bt] = t * 0.125f;
    }
}

__global__ __launch_bounds__(256) void aw_kernel()
{
    const int b = blockIdx.x;
    const int tid = threadIdx.x;
    float vals[8];
    float mn = 1e30f, mx = -1e30f;
    #pragma unroll
    for (int k = 0; k < 8; k++) {
        float v = g_pos[b * T_SEQ + tid + 256 * k];
        vals[k] = v;
        mn = fminf(mn, v);
        mx = fmaxf(mx, v);
    }
    __shared__ float smn[256], smx[256];
    smn[tid] = mn; smx[tid] = mx;
    __syncthreads();
    for (int s = 128; s; s >>= 1) {
        if (tid < s) {
            smn[tid] = fminf(smn[tid], smn[tid + s]);
            smx[tid] = fmaxf(smx[tid], smx[tid + s]);
        }
        __syncthreads();
    }
    const float gmn = smn[0];
    const float inv = 1.f / (smx[0] - smn[0] + 1e-6f);
    #pragma unroll
    for (int k = 0; k < 8; k++)
        g_aw[b * T_SEQ + tid + 256 * k] = (vals[k] - gmn) * inv;
}

// ---------------------------------------------------------------------------
// Flash attention — bf16x3, m16n8k16, P in registers (validated R8/R9).
// NEW: staging is now pure uint4 copies from the pre-split global arrays
// (no float4 loads, no bsplit2 in the hot loop).
// Smem 73728 B. 256 threads / 8 warps, Q-tile 128, K-chunk 64. 2 CTAs/SM.
// ---------------------------------------------------------------------------
static constexpr int FQS = 36;   // Q/K u32 row stride
static constexpr int FVS = 72;   // V u32 row stride
static constexpr int U_QH = 0;
static constexpr int U_QL = U_QH + 128 * FQS;   // 4608
static constexpr int U_KH = U_QL + 128 * FQS;   // 9216
static constexpr int U_KL = U_KH + 64 * FQS;    // 11520
static constexpr int U_VH = U_KL + 64 * FQS;    // 13824
static constexpr int U_VL = U_VH + 32 * FVS;    // 16128
static constexpr int FA_TOT = (U_VL + 32 * FVS) * 4;  // 73728 bytes

__global__ __launch_bounds__(256, 2) void flash_attn_tc()
{
    extern __shared__ uint32_t smu[];
    uint32_t* QH = smu + U_QH;
    uint32_t* QL = smu + U_QL;
    uint32_t* KH = smu + U_KH;
    uint32_t* KL = smu + U_KL;
    uint32_t* VH = smu + U_VH;
    uint32_t* VL = smu + U_VL;

    const int tid = threadIdx.x;
    const int wid = tid >> 5;
    const int lane = tid & 31;
    const int gid = lane >> 2, tig = lane & 3;
    const int bh  = blockIdx.y;
    const int b = bh >> 4, h = bh & 15;
    const int q0 = blockIdx.x * 128;

    // ---- Load Q tile (pre-split, prescaled): pure uint4 copies ----
    {
        const int r = tid >> 1, w0 = (tid & 1) * 16;
        const size_t gq = ((size_t)bh * T_SEQ + q0 + r) * 32 + w0;
        #pragma unroll
        for (int i = 0; i < 4; i++) {
            uint4 vh = *(const uint4*)(g_QH + gq + i * 4);
            uint4 vl = *(const uint4*)(g_QL + gq + i * 4);
            *(uint4*)(QH + r * FQS + w0 + i * 4) = vh;
            *(uint4*)(QL + r * FQS + w0 + i * 4) = vl;
        }
    }

    const int wq = wid * 16;   // warp's q-row offset within tile

    float m0 = -1e30f, m1 = -1e30f, l0v = 0.f, l1v = 0.f;
    float O[8][4];
    #pragma unroll
    for (int j = 0; j < 8; j++)
        #pragma unroll
        for (int q = 0; q < 4; q++) O[j][q] = 0.f;

    for (int t0 = 0; t0 < T_SEQ; t0 += 64) {
        __syncthreads();   // all warps done with previous K/V
        // ---- stage K: uint4 copies ----
        {
            const int r = tid >> 2, w0 = (tid & 3) * 8;
            const size_t gk = ((size_t)bh * T_SEQ + t0 + r) * 32 + w0;
            uint4 a = *(const uint4*)(g_KH + gk);
            uint4 c = *(const uint4*)(g_KH + gk + 4);
            *(uint4*)(KH + r * FQS + w0)     = a;
            *(uint4*)(KH + r * FQS + w0 + 4) = c;
            uint4 d = *(const uint4*)(g_KL + gk);
            uint4 e = *(const uint4*)(g_KL + gk + 4);
            *(uint4*)(KL + r * FQS + w0)     = d;
            *(uint4*)(KL + r * FQS + w0 + 4) = e;
        }
        // ---- stage V: uint4 copies ----
        {
            const int kp = tid >> 3, c0 = (tid & 7) * 8;
            const size_t gv = ((size_t)bh * (T_SEQ / 2) + t0 / 2 + kp) * 64 + c0;
            uint4 a = *(const uint4*)(g_VH + gv);
            uint4 c = *(const uint4*)(g_VH + gv + 4);
            *(uint4*)(VH + kp * FVS + c0)     = a;
            *(uint4*)(VH + kp * FVS + c0 + 4) = c;
            uint4 d = *(const uint4*)(g_VL + gv);
            uint4 e = *(const uint4*)(g_VL + gv + 4);
            *(uint4*)(VL + kp * FVS + c0)     = d;
            *(uint4*)(VL + kp * FVS + c0 + 4) = e;
        }
        __syncthreads();

        // ---- S = Q . K^T  (16 q-rows x 64 keys per warp), bf16x3 ----
        float s[8][4];
        #pragma unroll
        for (int j = 0; j < 8; j++)
            #pragma unroll
            for (int q = 0; q < 4; q++) s[j][q] = 0.f;
        #pragma unroll
        for (int ks = 0; ks < 4; ks++) {          // 4 x k16 over 64 channels
            uint32_t ah[4], al[4];
            frag_au(ah, QH, FQS, wq, ks * 8, gid, tig);
            frag_au(al, QL, FQS, wq, ks * 8, gid, tig);
            #pragma unroll
            for (int j = 0; j < 8; j++) {
                const int krow = (j * 8 + gid) * FQS + ks * 8 + tig;
                uint32_t bh_[2], bl_[2];
                bh_[0] = KH[krow]; bh_[1] = KH[krow + 4];
                bl_[0] = KL[krow]; bl_[1] = KL[krow + 4];
                mma_bf16(s[j], ah, bh_);
                mma_bf16(s[j], ah, bl_);
                mma_bf16(s[j], al, bh_);
            }
        }

        // ---- online softmax (rows gid and gid+8) ----
        float mx0 = -1e30f, mx1 = -1e30f;
        #pragma unroll
        for (int j = 0; j < 8; j++) {
            mx0 = fmaxf(mx0, fmaxf(s[j][0], s[j][1]));
            mx1 = fmaxf(mx1, fmaxf(s[j][2], s[j][3]));
        }
        #pragma unroll
        for (int msk = 1; msk < 4; msk <<= 1) {
            mx0 = fmaxf(mx0, __shfl_xor_sync(0xffffffffu, mx0, msk));
            mx1 = fmaxf(mx1, __shfl_xor_sync(0xffffffffu, mx1, msk));
        }
        const float mn0 = fmaxf(m0, mx0), mn1 = fmaxf(m1, mx1);
        const float al0 = __expf(m0 - mn0), al1 = __expf(m1 - mn1);
        m0 = mn0; m1 = mn1;
        float sum0 = 0.f, sum1 = 0.f;
        #pragma unroll
        for (int j = 0; j < 8; j++) {
            s[j][0] = __expf(s[j][0] - mn0); sum0 += s[j][0];
            s[j][1] = __expf(s[j][1] - mn0); sum0 += s[j][1];
            s[j][2] = __expf(s[j][2] - mn1); sum1 += s[j][2];
            s[j][3] = __expf(s[j][3] - mn1); sum1 += s[j][3];
        }
        #pragma unroll
        for (int msk = 1; msk < 4; msk <<= 1) {
            sum0 += __shfl_xor_sync(0xffffffffu, sum0, msk);
            sum1 += __shfl_xor_sync(0xffffffffu, sum1, msk);
        }
        l0v = l0v * al0 + sum0;
        l1v = l1v * al1 + sum1;
        #pragma unroll
        for (int j = 0; j < 8; j++) {
            O[j][0] *= al0; O[j][1] *= al0;
            O[j][2] *= al1; O[j][3] *= al1;
        }

        // ---- O += P . V : P built directly from the S C-fragment.
        #pragma unroll
        for (int kt = 0; kt < 4; kt++) {
            uint32_t ph[4], pl[4];
            bsplit2(s[2 * kt][0],     s[2 * kt][1],     ph[0], pl[0]);
            bsplit2(s[2 * kt][2],     s[2 * kt][3],     ph[1], pl[1]);
            bsplit2(s[2 * kt + 1][0], s[2 * kt + 1][1], ph[2], pl[2]);
            bsplit2(s[2 * kt + 1][2], s[2 * kt + 1][3], ph[3], pl[3]);
            #pragma unroll
            for (int j = 0; j < 8; j++) {
                const int vrow = (kt * 8 + tig) * FVS + j * 8 + gid;
                uint32_t bh_[2], bl_[2];
                bh_[0] = VH[vrow]; bh_[1] = VH[vrow + 4 * FVS];
                bl_[0] = VL[vrow]; bl_[1] = VL[vrow + 4 * FVS];
                mma_bf16(O[j], ph, bh_);
                mma_bf16(O[j], ph, bl_);
                mma_bf16(O[j], pl, bh_);
            }
        }
    }

    // ---- epilogue: normalize, apply adaptive weight, write g_attn ----
    const int t0r = q0 + wq + gid;
    const int t1r = t0r + 8;
    const float w0 = g_aw[b * T_SEQ + t0r] / l0v;
    const float w1 = g_aw[b * T_SEQ + t1r] / l1v;
    float* o0 = g_attn + (size_t)(b * T_SEQ + t0r) * WID + h * CH;
    float* o1 = g_attn + (size_t)(b * T_SEQ + t1r) * WID + h * CH;
    #pragma unroll
    for (int j = 0; j < 8; j++) {
        const int cc = j * 8 + 2 * tig;
        *(float2*)(o0 + cc) = make_float2(O[j][0] * w0, O[j][1] * w0);
        *(float2*)(o1 + cc) = make_float2(O[j][2] * w1, O[j][3] * w1);
    }
}

// ---------------------------------------------------------------------------
extern "C" void kernel_launch(void* const* d_in, const int* in_sizes, int n_in,
                              void* d_out, int out_size)
{
    const float* x     = (const float*)d_in[0];
    const float* Wqkv  = (const float*)d_in[1];
    const float* bqkv  = (const float*)d_in[2];
    const float* Wproj = (const float*)d_in[3];
    const float* bproj = (const float*)d_in[4];
    float* out = (float*)d_out;

    float *qkv, *attn;
    cudaGetSymbolAddress((void**)&qkv,  g_qkv);
    cudaGetSymbolAddress((void**)&attn, g_attn);

    static bool attr_set = false;
    if (!attr_set) {
        cudaFuncSetAttribute(gemm_bf16, cudaFuncAttributeMaxDynamicSharedMemorySize, G_TOT);
        cudaFuncSetAttribute(flash_attn_tc, cudaFuncAttributeMaxDynamicSharedMemorySize, FA_TOT);
        attr_set = true;
    }

    // 1) qkv = x @ W_qkv + b_qkv       (tensor, bf16x3)
    gemm_bf16<<<dim3(W3 / 128, MROWS / 128), 256, G_TOT>>>(x, Wqkv, bqkv, qkv, W3, WID);
    // 2) pre-split Q/K/V to bf16 hi/lo (once, instead of 16x inside flash)
    convert_kernel<<<dim3(T_SEQ / 64, BH_N), 256>>>();
    // 3) k_mean
    kmean_kernel<<<BATCH * HEADS, 256>>>();
    // 4) pos = (q . k_mean)/8
    pos_kernel<<<BATCH * T_SEQ, 256>>>();
    // 5) adaptive weight
    aw_kernel<<<BATCH, 256>>>();
    // 6) attention (tensor, bf16x3, copy-only staging; applies aw)
    flash_attn_tc<<<dim3(T_SEQ / 128, BH_N), 256, FA_TOT>>>();
    // 7) out = attn @ W_proj + b_proj  (tensor, bf16x3)
    gemm_bf16<<<dim3(WID / 128, MROWS / 128), 256, G_TOT>>>(attn, Wproj, bproj, out, WID, WID);
}

// round 11
// speedup vs baseline: 1.3096x; 1.3096x over previous
#include <cuda_runtime.h>
#include <cuda_fp16.h>
#include <cstdint>

// Problem constants
#define BATCH  2
#define T_SEQ  2048
#define WID    1024
#define HEADS  16
#define CH     64
#define W3     3072
#define MROWS  (BATCH * T_SEQ)   // 4096
#define BH_N   (BATCH * HEADS)   // 32

// Scratch (allocation-free rule: use __device__ globals)
__device__ float g_qkv [BATCH * T_SEQ * W3];    // 48 MB
__device__ float g_attn[BATCH * T_SEQ * WID];   // 16 MB
__device__ float g_kmean[BATCH * HEADS * CH];
__device__ float g_pos [BATCH * T_SEQ];
__device__ float g_aw  [BATCH * T_SEQ];

// ---------------------------------------------------------------------------
// mma.sync helpers (plain PTX — legal in compute_103 PTX)
// ---------------------------------------------------------------------------
__device__ __forceinline__ void mma_f16(float* c, const uint32_t* a, const uint32_t* b)
{
    asm volatile(
        "mma.sync.aligned.m16n8k16.row.col.f32.f16.f16.f32 "
        "{%0,%1,%2,%3}, {%4,%5,%6,%7}, {%8,%9}, {%0,%1,%2,%3};"
        : "+f"(c[0]), "+f"(c[1]), "+f"(c[2]), "+f"(c[3])
        : "r"(a[0]), "r"(a[1]), "r"(a[2]), "r"(a[3]),
          "r"(b[0]), "r"(b[1]));
}

// Pack two fp32 into one fp16x2 word (low half = first value).
__device__ __forceinline__ uint32_t fpack2(float x0, float x1)
{
    __half h0 = __float2half_rn(x0);
    __half h1 = __float2half_rn(x1);
    return (uint32_t)__half_as_ushort(h0) |
           ((uint32_t)__half_as_ushort(h1) << 16);
}

// Split two fp32 into packed fp16x2 hi + lo words (hi+lo exact to ~2^-22).
__device__ __forceinline__ void fsplit2(float x0, float x1,
                                        uint32_t& hi, uint32_t& lo)
{
    __half h0 = __float2half_rn(x0);
    __half h1 = __float2half_rn(x1);
    float f0 = __half2float(h0), f1 = __half2float(h1);
    hi = (uint32_t)__half_as_ushort(h0) |
         ((uint32_t)__half_as_ushort(h1) << 16);
    lo = fpack2(x0 - f0, x1 - f1);
}

// u32-packed A-frag (m16k16). lane = gid*4+tig; kw = k-word offset (k/2).
__device__ __forceinline__ void frag_au(uint32_t* a, const uint32_t* S, int SA,
                                        int r, int kw, int gid, int tig)
{
    const uint32_t* p0 = S + (r + gid) * SA + kw + tig;
    const uint32_t* p1 = S + (r + gid + 8) * SA + kw + tig;
    a[0] = p0[0]; a[1] = p1[0]; a[2] = p0[4]; a[3] = p1[4];
}

// ---------------------------------------------------------------------------
// Tensor-core GEMM, fp16 2-product (A split hi/lo, B single fp16):
// C = (Ah + Al) @ B16 + bias.  CTA tile 128x128, K-chunk 32, 256 threads,
// 8 warps (4M x 2N), warp tile 32x64.  Smem 29184 B.
// ---------------------------------------------------------------------------
static constexpr int BA_S = 20;    // A u32 row stride (16 words + pad)
static constexpr int BB_S = 136;   // B u32 kp-row stride (128 words + pad)
static constexpr int GB_AL = 128 * BA_S;             // 2560
static constexpr int GB_BH = 2 * 128 * BA_S;         // 5120
static constexpr int G_TOT = (GB_BH + 16 * BB_S) * 4; // 29184 bytes

__global__ __launch_bounds__(256) void gemm_f16(
    const float* __restrict__ A, const float* __restrict__ B,
    const float* __restrict__ bias, float* __restrict__ C,
    int N, int K)
{
    extern __shared__ uint32_t smu[];
    uint32_t* AH = smu;
    uint32_t* AL = smu + GB_AL;
    uint32_t* BH = smu + GB_BH;

    const int tid = threadIdx.x;
    const int wid = tid >> 5;
    const int lane = tid & 31;
    const int gid = lane >> 2, tig = lane & 3;
    const int wm = (wid >> 1) * 32;   // warp row offset in tile
    const int wn = (wid & 1) * 64;    // warp col offset in tile
    const int row0 = blockIdx.y * 128;
    const int col0 = blockIdx.x * 128;

    // stagers
    const int ar  = tid >> 1;           // 0..127
    const int ak  = (tid & 1) * 16;     // float offset 0 or 16
    const int bkp = tid >> 4;           // 0..15 (k-pair row)
    const int bn0 = (tid & 15) * 8;     // 0..120

    const float* Ap  = A + (size_t)(row0 + ar) * K + ak;
    const float* Bp0 = B + col0 + bn0;

    float c[2][8][4];
    #pragma unroll
    for (int i = 0; i < 2; i++)
        #pragma unroll
        for (int j = 0; j < 8; j++)
            #pragma unroll
            for (int q = 0; q < 4; q++) c[i][j][q] = 0.f;

    for (int kc = 0; kc < K; kc += 32) {
        __syncthreads();
        // ---- stage A (128 x 32 fp32 -> 128 x 16 u32 hi/lo) ----
        #pragma unroll
        for (int i = 0; i < 4; i++) {
            float4 v = *(const float4*)(Ap + kc + i * 4);
            uint32_t h0, l0, h1, l1;
            fsplit2(v.x, v.y, h0, l0);
            fsplit2(v.z, v.w, h1, l1);
            const int w = ar * BA_S + ak / 2 + i * 2;
            AH[w] = h0; AH[w + 1] = h1;
            AL[w] = l0; AL[w + 1] = l1;
        }
        // ---- stage B (32 x 128 fp32 -> 16 kp-rows x 128 u32, hi only) ----
        {
            const float* Bp = Bp0 + (size_t)(kc + 2 * bkp) * N;
            float4 x0 = *(const float4*)(Bp);
            float4 x1 = *(const float4*)(Bp + 4);
            float4 y0 = *(const float4*)(Bp + N);
            float4 y1 = *(const float4*)(Bp + N + 4);
            const float xa[8] = {x0.x, x0.y, x0.z, x0.w, x1.x, x1.y, x1.z, x1.w};
            const float ya[8] = {y0.x, y0.y, y0.z, y0.w, y1.x, y1.y, y1.z, y1.w};
            #pragma unroll
            for (int cI = 0; cI < 8; cI++)     // word = (B[k][n], B[k+1][n])
                BH[bkp * BB_S + bn0 + cI] = fpack2(xa[cI], ya[cI]);
        }
        __syncthreads();

        // ---- MMA: 2 x k16 steps, 2 products each ----
        #pragma unroll
        for (int ks = 0; ks < 2; ks++) {
            uint32_t ah[2][4], al_[2][4];
            frag_au(ah[0],  AH, BA_S, wm,      ks * 8, gid, tig);
            frag_au(ah[1],  AH, BA_S, wm + 16, ks * 8, gid, tig);
            frag_au(al_[0], AL, BA_S, wm,      ks * 8, gid, tig);
            frag_au(al_[1], AL, BA_S, wm + 16, ks * 8, gid, tig);
            #pragma unroll
            for (int j = 0; j < 8; j++) {
                const int base = (ks * 8 + tig) * BB_S + wn + j * 8 + gid;
                uint32_t bh[2];
                bh[0] = BH[base]; bh[1] = BH[base + 4 * BB_S];
                #pragma unroll
                for (int i = 0; i < 2; i++) {
                    mma_f16(c[i][j], ah[i],  bh);
                    mma_f16(c[i][j], al_[i], bh);
                }
            }
        }
    }

    // ---- epilogue: c frags + bias -> gmem ----
    #pragma unroll
    for (int i = 0; i < 2; i++) {
        const int r0 = row0 + wm + i * 16 + gid;
        #pragma unroll
        for (int j = 0; j < 8; j++) {
            const int col = col0 + wn + j * 8 + 2 * tig;
            float2 bv = *(const float2*)&bias[col];
            float2 o0 = make_float2(c[i][j][0] + bv.x, c[i][j][1] + bv.y);
            float2 o1 = make_float2(c[i][j][2] + bv.x, c[i][j][3] + bv.y);
            *(float2*)&C[(size_t)r0 * N + col]       = o0;
            *(float2*)&C[(size_t)(r0 + 8) * N + col] = o1;
        }
    }
}

// ---------------------------------------------------------------------------
// k_mean / pos / aw — unchanged
// ---------------------------------------------------------------------------
__global__ __launch_bounds__(256) void kmean_kernel()
{
    const int bh = blockIdx.x;
    const int b = bh >> 4, h = bh & 15;
    const int c  = threadIdx.x & 63;
    const int tg = threadIdx.x >> 6;
    const float* base = g_qkv + (size_t)b * T_SEQ * W3 + h * 192 + CH + c;
    float s = 0.f;
    for (int t = tg; t < T_SEQ; t += 4) s += base[(size_t)t * W3];
    __shared__ float red[4][64];
    red[tg][c] = s;
    __syncthreads();
    if (tg == 0) {
        float tot = red[0][c] + red[1][c] + red[2][c] + red[3][c];
        g_kmean[bh * CH + c] = tot * (1.f / (float)T_SEQ);
    }
}

__global__ __launch_bounds__(256) void pos_kernel()
{
    const int bt = blockIdx.x;
    const int b  = bt >> 11;
    const float* qb = g_qkv + (size_t)bt * W3;
    const float* km = g_kmean + b * WID;
    float s = 0.f;
    for (int j = threadIdx.x; j < WID; j += 256) {
        const int h = j >> 6, c = j & 63;
        s += qb[h * 192 + c] * km[j];
    }
    #pragma unroll
    for (int msk = 16; msk; msk >>= 1) s += __shfl_xor_sync(0xffffffffu, s, msk);
    __shared__ float red[8];
    if ((threadIdx.x & 31) == 0) red[threadIdx.x >> 5] = s;
    __syncthreads();
    if (threadIdx.x == 0) {
        float t = 0.f;
        #pragma unroll
        for (int w = 0; w < 8; w++) t += red[w];
        g_pos[bt] = t * 0.125f;
    }
}

__global__ __launch_bounds__(256) void aw_kernel()
{
    const int b = blockIdx.x;
    const int tid = threadIdx.x;
    float vals[8];
    float mn = 1e30f, mx = -1e30f;
    #pragma unroll
    for (int k = 0; k < 8; k++) {
        float v = g_pos[b * T_SEQ + tid + 256 * k];
        vals[k] = v;
        mn = fminf(mn, v);
        mx = fmaxf(mx, v);
    }
    __shared__ float smn[256], smx[256];
    smn[tid] = mn; smx[tid] = mx;
    __syncthreads();
    for (int s = 128; s; s >>= 1) {
        if (tid < s) {
            smn[tid] = fminf(smn[tid], smn[tid + s]);
            smx[tid] = fmaxf(smx[tid], smx[tid + s]);
        }
        __syncthreads();
    }
    const float gmn = smn[0];
    const float inv = 1.f / (smx[0] - smn[0] + 1e-6f);
    #pragma unroll
    for (int k = 0; k < 8; k++)
        g_aw[b * T_SEQ + tid + 256 * k] = (vals[k] - gmn) * inv;
}

// ---------------------------------------------------------------------------
// Flash attention — fp16 2-product, m16n8k16, P in registers.
// Q split hi/lo, K single fp16 (S-pass); P split hi/lo, V single (PV-pass).
// Smem 55296 B (no KL/VL). 256 threads / 8 warps, Q-tile 128, K-chunk 64.
// R9 staging structure (split in-kernel; R10's pre-split regressed, reverted).
// ---------------------------------------------------------------------------
static constexpr int FQS = 36;   // Q/K u32 row stride
static constexpr int FVS = 72;   // V u32 row stride
static constexpr int U_QH = 0;
static constexpr int U_QL = U_QH + 128 * FQS;   // 4608
static constexpr int U_KH = U_QL + 128 * FQS;   // 9216
static constexpr int U_VH = U_KH + 64 * FQS;    // 11520
static constexpr int FA_TOT = (U_VH + 32 * FVS) * 4;  // 55296 bytes

__global__ __launch_bounds__(256, 2) void flash_attn_tc()
{
    extern __shared__ uint32_t smu[];
    uint32_t* QH = smu + U_QH;
    uint32_t* QL = smu + U_QL;
    uint32_t* KH = smu + U_KH;
    uint32_t* VH = smu + U_VH;

    const int tid = threadIdx.x;
    const int wid = tid >> 5;
    const int lane = tid & 31;
    const int gid = lane >> 2, tig = lane & 3;
    const int bh  = blockIdx.y;
    const int b = bh >> 4, h = bh & 15;
    const int q0 = blockIdx.x * 128;
    const float* base = g_qkv + (size_t)b * T_SEQ * W3 + h * 192;

    // ---- Load Q tile (128 rows): prescale 1/8, fp16-split, pack pairs ----
    {
        const int r = tid >> 1, c0 = (tid & 1) * 32;
        const float* qrow = base + (size_t)(q0 + r) * W3 + c0;
        #pragma unroll
        for (int i = 0; i < 8; i++) {
            float4 v = *(const float4*)(qrow + i * 4);
            uint32_t h0, l0, h1, l1;
            fsplit2(v.x * 0.125f, v.y * 0.125f, h0, l0);
            fsplit2(v.z * 0.125f, v.w * 0.125f, h1, l1);
            const int w = r * FQS + c0 / 2 + i * 2;
            QH[w] = h0; QH[w + 1] = h1;
            QL[w] = l0; QL[w + 1] = l1;
        }
    }

    const int wq = wid * 16;   // warp's q-row offset within tile

    float m0 = -1e30f, m1 = -1e30f, l0v = 0.f, l1v = 0.f;
    float O[8][4];
    #pragma unroll
    for (int j = 0; j < 8; j++)
        #pragma unroll
        for (int q = 0; q < 4; q++) O[j][q] = 0.f;

    for (int t0 = 0; t0 < T_SEQ; t0 += 64) {
        __syncthreads();   // all warps done with previous K/V
        // ---- stage K (single fp16): 64 keys x 64 ch, packed along ch ----
        {
            const int r = tid >> 2, c0 = (tid & 3) * 16;
            const float* krow = base + (size_t)(t0 + r) * W3 + CH + c0;
            #pragma unroll
            for (int i = 0; i < 4; i++) {
                float4 v = *(const float4*)(krow + i * 4);
                const int w = r * FQS + c0 / 2 + i * 2;
                KH[w]     = fpack2(v.x, v.y);
                KH[w + 1] = fpack2(v.z, v.w);
            }
        }
        // ---- stage V (single fp16): word = (V[2kp][c], V[2kp+1][c]) ----
        {
            const int kp = tid >> 3, c0 = (tid & 7) * 8;
            const float* v0 = base + (size_t)(t0 + 2 * kp) * W3 + 2 * CH + c0;
            const float* v1 = v0 + W3;
            float4 a0 = *(const float4*)(v0);
            float4 a1 = *(const float4*)(v0 + 4);
            float4 b0 = *(const float4*)(v1);
            float4 b1 = *(const float4*)(v1 + 4);
            const float va[8] = {a0.x, a0.y, a0.z, a0.w, a1.x, a1.y, a1.z, a1.w};
            const float vb[8] = {b0.x, b0.y, b0.z, b0.w, b1.x, b1.y, b1.z, b1.w};
            #pragma unroll
            for (int c = 0; c < 8; c++)
                VH[kp * FVS + c0 + c] = fpack2(va[c], vb[c]);
        }
        __syncthreads();

        // ---- S = Q . K^T  (16 q-rows x 64 keys per warp), 2 products ----
        float s[8][4];
        #pragma unroll
        for (int j = 0; j < 8; j++)
            #pragma unroll
            for (int q = 0; q < 4; q++) s[j][q] = 0.f;
        #pragma unroll
        for (int ks = 0; ks < 4; ks++) {          // 4 x k16 over 64 channels
            uint32_t ah[4], al[4];
            frag_au(ah, QH, FQS, wq, ks * 8, gid, tig);
            frag_au(al, QL, FQS, wq, ks * 8, gid, tig);
            #pragma unroll
            for (int j = 0; j < 8; j++) {
                const int krow = (j * 8 + gid) * FQS + ks * 8 + tig;
                uint32_t bh_[2];
                bh_[0] = KH[krow]; bh_[1] = KH[krow + 4];
                mma_f16(s[j], ah, bh_);
                mma_f16(s[j], al, bh_);
            }
        }

        // ---- online softmax (rows gid and gid+8) ----
        float mx0 = -1e30f, mx1 = -1e30f;
        #pragma unroll
        for (int j = 0; j < 8; j++) {
            mx0 = fmaxf(mx0, fmaxf(s[j][0], s[j][1]));
            mx1 = fmaxf(mx1, fmaxf(s[j][2], s[j][3]));
        }
        #pragma unroll
        for (int msk = 1; msk < 4; msk <<= 1) {
            mx0 = fmaxf(mx0, __shfl_xor_sync(0xffffffffu, mx0, msk));
            mx1 = fmaxf(mx1, __shfl_xor_sync(0xffffffffu, mx1, msk));
        }
        const float mn0 = fmaxf(m0, mx0), mn1 = fmaxf(m1, mx1);
        const float al0 = __expf(m0 - mn0), al1 = __expf(m1 - mn1);
        m0 = mn0; m1 = mn1;
        float sum0 = 0.f, sum1 = 0.f;
        #pragma unroll
        for (int j = 0; j < 8; j++) {
            s[j][0] = __expf(s[j][0] - mn0); sum0 += s[j][0];
            s[j][1] = __expf(s[j][1] - mn0); sum0 += s[j][1];
            s[j][2] = __expf(s[j][2] - mn1); sum1 += s[j][2];
            s[j][3] = __expf(s[j][3] - mn1); sum1 += s[j][3];
        }
        #pragma unroll
        for (int msk = 1; msk < 4; msk <<= 1) {
            sum0 += __shfl_xor_sync(0xffffffffu, sum0, msk);
            sum1 += __shfl_xor_sync(0xffffffffu, sum1, msk);
        }
        l0v = l0v * al0 + sum0;
        l1v = l1v * al1 + sum1;
        #pragma unroll
        for (int j = 0; j < 8; j++) {
            O[j][0] *= al0; O[j][1] *= al0;
            O[j][2] *= al1; O[j][3] *= al1;
        }

        // ---- O += P . V : P split hi/lo from the S C-fragment, V single ----
        #pragma unroll
        for (int kt = 0; kt < 4; kt++) {
            uint32_t ph[4], pl[4];
            fsplit2(s[2 * kt][0],     s[2 * kt][1],     ph[0], pl[0]);
            fsplit2(s[2 * kt][2],     s[2 * kt][3],     ph[1], pl[1]);
            fsplit2(s[2 * kt + 1][0], s[2 * kt + 1][1], ph[2], pl[2]);
            fsplit2(s[2 * kt + 1][2], s[2 * kt + 1][3], ph[3], pl[3]);
            #pragma unroll
            for (int j = 0; j < 8; j++) {
                const int vrow = (kt * 8 + tig) * FVS + j * 8 + gid;
                uint32_t vh_[2];
                vh_[0] = VH[vrow]; vh_[1] = VH[vrow + 4 * FVS];
                mma_f16(O[j], ph, vh_);
                mma_f16(O[j], pl, vh_);
            }
        }
    }

    // ---- epilogue: normalize, apply adaptive weight, write g_attn ----
    const int t0r = q0 + wq + gid;
    const int t1r = t0r + 8;
    const float w0 = g_aw[b * T_SEQ + t0r] / l0v;
    const float w1 = g_aw[b * T_SEQ + t1r] / l1v;
    float* o0 = g_attn + (size_t)(b * T_SEQ + t0r) * WID + h * CH;
    float* o1 = g_attn + (size_t)(b * T_SEQ + t1r) * WID + h * CH;
    #pragma unroll
    for (int j = 0; j < 8; j++) {
        const int cc = j * 8 + 2 * tig;
        *(float2*)(o0 + cc) = make_float2(O[j][0] * w0, O[j][1] * w0);
        *(float2*)(o1 + cc) = make_float2(O[j][2] * w1, O[j][3] * w1);
    }
}

// ---------------------------------------------------------------------------
extern "C" void kernel_launch(void* const* d_in, const int* in_sizes, int n_in,
                              void* d_out, int out_size)
{
    const float* x     = (const float*)d_in[0];
    const float* Wqkv  = (const float*)d_in[1];
    const float* bqkv  = (const float*)d_in[2];
    const float* Wproj = (const float*)d_in[3];
    const float* bproj = (const float*)d_in[4];
    float* out = (float*)d_out;

    float *qkv, *attn;
    cudaGetSymbolAddress((void**)&qkv,  g_qkv);
    cudaGetSymbolAddress((void**)&attn, g_attn);

    static bool attr_set = false;
    if (!attr_set) {
        cudaFuncSetAttribute(gemm_f16, cudaFuncAttributeMaxDynamicSharedMemorySize, G_TOT);
        cudaFuncSetAttribute(flash_attn_tc, cudaFuncAttributeMaxDynamicSharedMemorySize, FA_TOT);
        attr_set = true;
    }

    // 1) qkv = x @ W_qkv + b_qkv       (tensor, fp16 2-product)
    gemm_f16<<<dim3(W3 / 128, MROWS / 128), 256, G_TOT>>>(x, Wqkv, bqkv, qkv, W3, WID);
    // 2) k_mean
    kmean_kernel<<<BATCH * HEADS, 256>>>();
    // 3) pos = (q . k_mean)/8
    pos_kernel<<<BATCH * T_SEQ, 256>>>();
    // 4) adaptive weight
    aw_kernel<<<BATCH, 256>>>();
    // 5) attention (tensor, fp16 2-product, P in registers; applies aw)
    flash_attn_tc<<<dim3(T_SEQ / 128, BH_N), 256, FA_TOT>>>();
    // 6) out = attn @ W_proj + b_proj  (tensor, fp16 2-product)
    gemm_f16<<<dim3(WID / 128, MROWS / 128), 256, G_TOT>>>(attn, Wproj, bproj, out, WID, WID);
}

// round 12
// speedup vs baseline: 1.6510x; 1.2607x over previous
#include <cuda_runtime.h>
#include <cuda_fp16.h>
#include <cstdint>

// Problem constants
#define BATCH  2
#define T_SEQ  2048
#define WID    1024
#define HEADS  16
#define CH     64
#define W3     3072
#define MROWS  (BATCH * T_SEQ)   // 4096
#define BH_N   (BATCH * HEADS)   // 32

// Scratch (allocation-free rule: use __device__ globals)
__device__ float g_qkv [BATCH * T_SEQ * W3];    // 48 MB
__device__ float g_attn[BATCH * T_SEQ * WID];   // 16 MB
__device__ float g_kmean[BATCH * HEADS * CH];
__device__ float g_pos [BATCH * T_SEQ];
__device__ float g_aw  [BATCH * T_SEQ];

// ---------------------------------------------------------------------------
// mma.sync helpers (plain PTX — legal in compute_103 PTX)
// ---------------------------------------------------------------------------
__device__ __forceinline__ void mma_f16(float* c, const uint32_t* a, const uint32_t* b)
{
    asm volatile(
        "mma.sync.aligned.m16n8k16.row.col.f32.f16.f16.f32 "
        "{%0,%1,%2,%3}, {%4,%5,%6,%7}, {%8,%9}, {%0,%1,%2,%3};"
        : "+f"(c[0]), "+f"(c[1]), "+f"(c[2]), "+f"(c[3])
        : "r"(a[0]), "r"(a[1]), "r"(a[2]), "r"(a[3]),
          "r"(b[0]), "r"(b[1]));
}

// Pack two fp32 into one fp16x2 word (low half = first value).
__device__ __forceinline__ uint32_t fpack2(float x0, float x1)
{
    __half h0 = __float2half_rn(x0);
    __half h1 = __float2half_rn(x1);
    return (uint32_t)__half_as_ushort(h0) |
           ((uint32_t)__half_as_ushort(h1) << 16);
}

// u32-packed A-frag (m16k16). lane = gid*4+tig; kw = k-word offset (k/2).
__device__ __forceinline__ void frag_au(uint32_t* a, const uint32_t* S, int SA,
                                        int r, int kw, int gid, int tig)
{
    const uint32_t* p0 = S + (r + gid) * SA + kw + tig;
    const uint32_t* p1 = S + (r + gid + 8) * SA + kw + tig;
    a[0] = p0[0]; a[1] = p1[0]; a[2] = p0[4]; a[3] = p1[4];
}

// ---------------------------------------------------------------------------
// Tensor-core GEMM, single fp16 product: C = A16 @ B16 + bias.
// CTA tile 128x128, K-chunk 32, 256 threads, 8 warps (4M x 2N),
// warp tile 32x64.  Smem 18944 B.
// ---------------------------------------------------------------------------
static constexpr int BA_S = 20;    // A u32 row stride (16 words + pad)
static constexpr int BB_S = 136;   // B u32 kp-row stride (128 words + pad)
static constexpr int GB_BH = 128 * BA_S;              // 2560
static constexpr int G_TOT = (GB_BH + 16 * BB_S) * 4; // 18944 bytes

__global__ __launch_bounds__(256) void gemm_f16(
    const float* __restrict__ A, const float* __restrict__ B,
    const float* __restrict__ bias, float* __restrict__ C,
    int N, int K)
{
    extern __shared__ uint32_t smu[];
    uint32_t* AH = smu;
    uint32_t* BH = smu + GB_BH;

    const int tid = threadIdx.x;
    const int wid = tid >> 5;
    const int lane = tid & 31;
    const int gid = lane >> 2, tig = lane & 3;
    const int wm = (wid >> 1) * 32;   // warp row offset in tile
    const int wn = (wid & 1) * 64;    // warp col offset in tile
    const int row0 = blockIdx.y * 128;
    const int col0 = blockIdx.x * 128;

    // stagers
    const int ar  = tid >> 1;           // 0..127
    const int ak  = (tid & 1) * 16;     // float offset 0 or 16
    const int bkp = tid >> 4;           // 0..15 (k-pair row)
    const int bn0 = (tid & 15) * 8;     // 0..120

    const float* Ap  = A + (size_t)(row0 + ar) * K + ak;
    const float* Bp0 = B + col0 + bn0;

    float c[2][8][4];
    #pragma unroll
    for (int i = 0; i < 2; i++)
        #pragma unroll
        for (int j = 0; j < 8; j++)
            #pragma unroll
            for (int q = 0; q < 4; q++) c[i][j][q] = 0.f;

    for (int kc = 0; kc < K; kc += 32) {
        __syncthreads();
        // ---- stage A (128 x 32 fp32 -> 128 x 16 u32 fp16x2) ----
        #pragma unroll
        for (int i = 0; i < 4; i++) {
            float4 v = *(const float4*)(Ap + kc + i * 4);
            const int w = ar * BA_S + ak / 2 + i * 2;
            AH[w]     = fpack2(v.x, v.y);
            AH[w + 1] = fpack2(v.z, v.w);
        }
        // ---- stage B (32 x 128 fp32 -> 16 kp-rows x 128 u32) ----
        {
            const float* Bp = Bp0 + (size_t)(kc + 2 * bkp) * N;
            float4 x0 = *(const float4*)(Bp);
            float4 x1 = *(const float4*)(Bp + 4);
            float4 y0 = *(const float4*)(Bp + N);
            float4 y1 = *(const float4*)(Bp + N + 4);
            const float xa[8] = {x0.x, x0.y, x0.z, x0.w, x1.x, x1.y, x1.z, x1.w};
            const float ya[8] = {y0.x, y0.y, y0.z, y0.w, y1.x, y1.y, y1.z, y1.w};
            #pragma unroll
            for (int cI = 0; cI < 8; cI++)     // word = (B[k][n], B[k+1][n])
                BH[bkp * BB_S + bn0 + cI] = fpack2(xa[cI], ya[cI]);
        }
        __syncthreads();

        // ---- MMA: 2 x k16 steps, single product ----
        #pragma unroll
        for (int ks = 0; ks < 2; ks++) {
            uint32_t ah[2][4];
            frag_au(ah[0], AH, BA_S, wm,      ks * 8, gid, tig);
            frag_au(ah[1], AH, BA_S, wm + 16, ks * 8, gid, tig);
            #pragma unroll
            for (int j = 0; j < 8; j++) {
                const int base = (ks * 8 + tig) * BB_S + wn + j * 8 + gid;
                uint32_t bh[2];
                bh[0] = BH[base]; bh[1] = BH[base + 4 * BB_S];
                mma_f16(c[0][j], ah[0], bh);
                mma_f16(c[1][j], ah[1], bh);
            }
        }
    }

    // ---- epilogue: c frags + bias -> gmem ----
    #pragma unroll
    for (int i = 0; i < 2; i++) {
        const int r0 = row0 + wm + i * 16 + gid;
        #pragma unroll
        for (int j = 0; j < 8; j++) {
            const int col = col0 + wn + j * 8 + 2 * tig;
            float2 bv = *(const float2*)&bias[col];
            float2 o0 = make_float2(c[i][j][0] + bv.x, c[i][j][1] + bv.y);
            float2 o1 = make_float2(c[i][j][2] + bv.x, c[i][j][3] + bv.y);
            *(float2*)&C[(size_t)r0 * N + col]       = o0;
            *(float2*)&C[(size_t)(r0 + 8) * N + col] = o1;
        }
    }
}

// ---------------------------------------------------------------------------
// k_mean / pos / aw — unchanged
// ---------------------------------------------------------------------------
__global__ __launch_bounds__(256) void kmean_kernel()
{
    const int bh = blockIdx.x;
    const int b = bh >> 4, h = bh & 15;
    const int c  = threadIdx.x & 63;
    const int tg = threadIdx.x >> 6;
    const float* base = g_qkv + (size_t)b * T_SEQ * W3 + h * 192 + CH + c;
    float s = 0.f;
    for (int t = tg; t < T_SEQ; t += 4) s += base[(size_t)t * W3];
    __shared__ float red[4][64];
    red[tg][c] = s;
    __syncthreads();
    if (tg == 0) {
        float tot = red[0][c] + red[1][c] + red[2][c] + red[3][c];
        g_kmean[bh * CH + c] = tot * (1.f / (float)T_SEQ);
    }
}

__global__ __launch_bounds__(256) void pos_kernel()
{
    const int bt = blockIdx.x;
    const int b  = bt >> 11;
    const float* qb = g_qkv + (size_t)bt * W3;
    const float* km = g_kmean + b * WID;
    float s = 0.f;
    for (int j = threadIdx.x; j < WID; j += 256) {
        const int h = j >> 6, c = j & 63;
        s += qb[h * 192 + c] * km[j];
    }
    #pragma unroll
    for (int msk = 16; msk; msk >>= 1) s += __shfl_xor_sync(0xffffffffu, s, msk);
    __shared__ float red[8];
    if ((threadIdx.x & 31) == 0) red[threadIdx.x >> 5] = s;
    __syncthreads();
    if (threadIdx.x == 0) {
        float t = 0.f;
        #pragma unroll
        for (int w = 0; w < 8; w++) t += red[w];
        g_pos[bt] = t * 0.125f;
    }
}

__global__ __launch_bounds__(256) void aw_kernel()
{
    const int b = blockIdx.x;
    const int tid = threadIdx.x;
    float vals[8];
    float mn = 1e30f, mx = -1e30f;
    #pragma unroll
    for (int k = 0; k < 8; k++) {
        float v = g_pos[b * T_SEQ + tid + 256 * k];
        vals[k] = v;
        mn = fminf(mn, v);
        mx = fmaxf(mx, v);
    }
    __shared__ float smn[256], smx[256];
    smn[tid] = mn; smx[tid] = mx;
    __syncthreads();
    for (int s = 128; s; s >>= 1) {
        if (tid < s) {
            smn[tid] = fminf(smn[tid], smn[tid + s]);
            smx[tid] = fmaxf(smx[tid], smx[tid + s]);
        }
        __syncthreads();
    }
    const float gmn = smn[0];
    const float inv = 1.f / (smx[0] - smn[0] + 1e-6f);
    #pragma unroll
    for (int k = 0; k < 8; k++)
        g_aw[b * T_SEQ + tid + 256 * k] = (vals[k] - gmn) * inv;
}

// ---------------------------------------------------------------------------
// Flash attention — single fp16, m16n8k16, P in registers.
// Q single (prescaled 1/8), K single; P single from S C-fragment, V single.
// Smem 36864 B. 256 threads / 8 warps, Q-tile 128, K-chunk 64.
// ---------------------------------------------------------------------------
static constexpr int FQS = 36;   // Q/K u32 row stride
static constexpr int FVS = 72;   // V u32 row stride
static constexpr int U_QH = 0;
static constexpr int U_KH = U_QH + 128 * FQS;   // 4608
static constexpr int U_VH = U_KH + 64 * FQS;    // 6912
static constexpr int FA_TOT = (U_VH + 32 * FVS) * 4;  // 36864 bytes

__global__ __launch_bounds__(256, 2) void flash_attn_tc()
{
    extern __shared__ uint32_t smu[];
    uint32_t* QH = smu + U_QH;
    uint32_t* KH = smu + U_KH;
    uint32_t* VH = smu + U_VH;

    const int tid = threadIdx.x;
    const int wid = tid >> 5;
    const int lane = tid & 31;
    const int gid = lane >> 2, tig = lane & 3;
    const int bh  = blockIdx.y;
    const int b = bh >> 4, h = bh & 15;
    const int q0 = blockIdx.x * 128;
    const float* base = g_qkv + (size_t)b * T_SEQ * W3 + h * 192;

    // ---- Load Q tile (128 rows): prescale 1/8, single fp16, pack pairs ----
    {
        const int r = tid >> 1, c0 = (tid & 1) * 32;
        const float* qrow = base + (size_t)(q0 + r) * W3 + c0;
        #pragma unroll
        for (int i = 0; i < 8; i++) {
            float4 v = *(const float4*)(qrow + i * 4);
            const int w = r * FQS + c0 / 2 + i * 2;
            QH[w]     = fpack2(v.x * 0.125f, v.y * 0.125f);
            QH[w + 1] = fpack2(v.z * 0.125f, v.w * 0.125f);
        }
    }

    const int wq = wid * 16;   // warp's q-row offset within tile

    float m0 = -1e30f, m1 = -1e30f, l0v = 0.f, l1v = 0.f;
    float O[8][4];
    #pragma unroll
    for (int j = 0; j < 8; j++)
        #pragma unroll
        for (int q = 0; q < 4; q++) O[j][q] = 0.f;

    for (int t0 = 0; t0 < T_SEQ; t0 += 64) {
        __syncthreads();   // all warps done with previous K/V
        // ---- stage K (single fp16): 64 keys x 64 ch, packed along ch ----
        {
            const int r = tid >> 2, c0 = (tid & 3) * 16;
            const float* krow = base + (size_t)(t0 + r) * W3 + CH + c0;
            #pragma unroll
            for (int i = 0; i < 4; i++) {
                float4 v = *(const float4*)(krow + i * 4);
                const int w = r * FQS + c0 / 2 + i * 2;
                KH[w]     = fpack2(v.x, v.y);
                KH[w + 1] = fpack2(v.z, v.w);
            }
        }
        // ---- stage V (single fp16): word = (V[2kp][c], V[2kp+1][c]) ----
        {
            const int kp = tid >> 3, c0 = (tid & 7) * 8;
            const float* v0 = base + (size_t)(t0 + 2 * kp) * W3 + 2 * CH + c0;
            const float* v1 = v0 + W3;
            float4 a0 = *(const float4*)(v0);
            float4 a1 = *(const float4*)(v0 + 4);
            float4 b0 = *(const float4*)(v1);
            float4 b1 = *(const float4*)(v1 + 4);
            const float va[8] = {a0.x, a0.y, a0.z, a0.w, a1.x, a1.y, a1.z, a1.w};
            const float vb[8] = {b0.x, b0.y, b0.z, b0.w, b1.x, b1.y, b1.z, b1.w};
            #pragma unroll
            for (int c = 0; c < 8; c++)
                VH[kp * FVS + c0 + c] = fpack2(va[c], vb[c]);
        }
        __syncthreads();

        // ---- S = Q . K^T  (16 q-rows x 64 keys per warp), single ----
        float s[8][4];
        #pragma unroll
        for (int j = 0; j < 8; j++)
            #pragma unroll
            for (int q = 0; q < 4; q++) s[j][q] = 0.f;
        #pragma unroll
        for (int ks = 0; ks < 4; ks++) {          // 4 x k16 over 64 channels
            uint32_t ah[4];
            frag_au(ah, QH, FQS, wq, ks * 8, gid, tig);
            #pragma unroll
            for (int j = 0; j < 8; j++) {
                const int krow = (j * 8 + gid) * FQS + ks * 8 + tig;
                uint32_t bh_[2];
                bh_[0] = KH[krow]; bh_[1] = KH[krow + 4];
                mma_f16(s[j], ah, bh_);
            }
        }

        // ---- online softmax (rows gid and gid+8) ----
        float mx0 = -1e30f, mx1 = -1e30f;
        #pragma unroll
        for (int j = 0; j < 8; j++) {
            mx0 = fmaxf(mx0, fmaxf(s[j][0], s[j][1]));
            mx1 = fmaxf(mx1, fmaxf(s[j][2], s[j][3]));
        }
        #pragma unroll
        for (int msk = 1; msk < 4; msk <<= 1) {
            mx0 = fmaxf(mx0, __shfl_xor_sync(0xffffffffu, mx0, msk));
            mx1 = fmaxf(mx1, __shfl_xor_sync(0xffffffffu, mx1, msk));
        }
        const float mn0 = fmaxf(m0, mx0), mn1 = fmaxf(m1, mx1);
        const float al0 = __expf(m0 - mn0), al1 = __expf(m1 - mn1);
        m0 = mn0; m1 = mn1;
        float sum0 = 0.f, sum1 = 0.f;
        #pragma unroll
        for (int j = 0; j < 8; j++) {
            s[j][0] = __expf(s[j][0] - mn0); sum0 += s[j][0];
            s[j][1] = __expf(s[j][1] - mn0); sum0 += s[j][1];
            s[j][2] = __expf(s[j][2] - mn1); sum1 += s[j][2];
            s[j][3] = __expf(s[j][3] - mn1); sum1 += s[j][3];
        }
        #pragma unroll
        for (int msk = 1; msk < 4; msk <<= 1) {
            sum0 += __shfl_xor_sync(0xffffffffu, sum0, msk);
            sum1 += __shfl_xor_sync(0xffffffffu, sum1, msk);
        }
        l0v = l0v * al0 + sum0;
        l1v = l1v * al1 + sum1;
        #pragma unroll
        for (int j = 0; j < 8; j++) {
            O[j][0] *= al0; O[j][1] *= al0;
            O[j][2] *= al1; O[j][3] *= al1;
        }

        // ---- O += P . V : P single fp16 straight from S C-fragment ----
        #pragma unroll
        for (int kt = 0; kt < 4; kt++) {
            uint32_t ph[4];
            ph[0] = fpack2(s[2 * kt][0],     s[2 * kt][1]);
            ph[1] = fpack2(s[2 * kt][2],     s[2 * kt][3]);
            ph[2] = fpack2(s[2 * kt + 1][0], s[2 * kt + 1][1]);
            ph[3] = fpack2(s[2 * kt + 1][2], s[2 * kt + 1][3]);
            #pragma unroll
            for (int j = 0; j < 8; j++) {
                const int vrow = (kt * 8 + tig) * FVS + j * 8 + gid;
                uint32_t vh_[2];
                vh_[0] = VH[vrow]; vh_[1] = VH[vrow + 4 * FVS];
                mma_f16(O[j], ph, vh_);
            }
        }
    }

    // ---- epilogue: normalize, apply adaptive weight, write g_attn ----
    const int t0r = q0 + wq + gid;
    const int t1r = t0r + 8;
    const float w0 = g_aw[b * T_SEQ + t0r] / l0v;
    const float w1 = g_aw[b * T_SEQ + t1r] / l1v;
    float* o0 = g_attn + (size_t)(b * T_SEQ + t0r) * WID + h * CH;
    float* o1 = g_attn + (size_t)(b * T_SEQ + t1r) * WID + h * CH;
    #pragma unroll
    for (int j = 0; j < 8; j++) {
        const int cc = j * 8 + 2 * tig;
        *(float2*)(o0 + cc) = make_float2(O[j][0] * w0, O[j][1] * w0);
        *(float2*)(o1 + cc) = make_float2(O[j][2] * w1, O[j][3] * w1);
    }
}

// ---------------------------------------------------------------------------
extern "C" void kernel_launch(void* const* d_in, const int* in_sizes, int n_in,
                              void* d_out, int out_size)
{
    const float* x     = (const float*)d_in[0];
    const float* Wqkv  = (const float*)d_in[1];
    const float* bqkv  = (const float*)d_in[2];
    const float* Wproj = (const float*)d_in[3];
    const float* bproj = (const float*)d_in[4];
    float* out = (float*)d_out;

    float *qkv, *attn;
    cudaGetSymbolAddress((void**)&qkv,  g_qkv);
    cudaGetSymbolAddress((void**)&attn, g_attn);

    static bool attr_set = false;
    if (!attr_set) {
        cudaFuncSetAttribute(gemm_f16, cudaFuncAttributeMaxDynamicSharedMemorySize, G_TOT);
        cudaFuncSetAttribute(flash_attn_tc, cudaFuncAttributeMaxDynamicSharedMemorySize, FA_TOT);
        attr_set = true;
    }

    // 1) qkv = x @ W_qkv + b_qkv       (tensor, single fp16)
    gemm_f16<<<dim3(W3 / 128, MROWS / 128), 256, G_TOT>>>(x, Wqkv, bqkv, qkv, W3, WID);
    // 2) k_mean
    kmean_kernel<<<BATCH * HEADS, 256>>>();
    // 3) pos = (q . k_mean)/8
    pos_kernel<<<BATCH * T_SEQ, 256>>>();
    // 4) adaptive weight
    aw_kernel<<<BATCH, 256>>>();
    // 5) attention (tensor, single fp16, P in registers; applies aw)
    flash_attn_tc<<<dim3(T_SEQ / 128, BH_N), 256, FA_TOT>>>();
    // 6) out = attn @ W_proj + b_proj  (tensor, single fp16)
    gemm_f16<<<dim3(WID / 128, MROWS / 128), 256, G_TOT>>>(attn, Wproj, bproj, out, WID, WID);
}

// round 13
// speedup vs baseline: 1.7214x; 1.0426x over previous
#include <cuda_runtime.h>
#include <cuda_fp16.h>
#include <cstdint>

// Problem constants
#define BATCH  2
#define T_SEQ  2048
#define WID    1024
#define HEADS  16
#define CH     64
#define W3     3072
#define MROWS  (BATCH * T_SEQ)   // 4096
#define BH_N   (BATCH * HEADS)   // 32

// Scratch (allocation-free rule: use __device__ globals)
__device__ float g_qkv [BATCH * T_SEQ * W3];    // 48 MB
__device__ float g_attn[BATCH * T_SEQ * WID];   // 16 MB
__device__ float g_kmean[BATCH * HEADS * CH];
__device__ float g_pos [BATCH * T_SEQ];
__device__ float g_aw  [BATCH * T_SEQ];

// ---------------------------------------------------------------------------
// mma.sync helpers (plain PTX — legal in compute_103 PTX)
// ---------------------------------------------------------------------------
__device__ __forceinline__ void mma_f16(float* c, const uint32_t* a, const uint32_t* b)
{
    asm volatile(
        "mma.sync.aligned.m16n8k16.row.col.f32.f16.f16.f32 "
        "{%0,%1,%2,%3}, {%4,%5,%6,%7}, {%8,%9}, {%0,%1,%2,%3};"
        : "+f"(c[0]), "+f"(c[1]), "+f"(c[2]), "+f"(c[3])
        : "r"(a[0]), "r"(a[1]), "r"(a[2]), "r"(a[3]),
          "r"(b[0]), "r"(b[1]));
}

// Pack two fp32 into one fp16x2 word (low half = first value).
__device__ __forceinline__ uint32_t fpack2(float x0, float x1)
{
    __half h0 = __float2half_rn(x0);
    __half h1 = __float2half_rn(x1);
    return (uint32_t)__half_as_ushort(h0) |
           ((uint32_t)__half_as_ushort(h1) << 16);
}

// u32-packed A-frag (m16k16). lane = gid*4+tig; kw = k-word offset (k/2).
__device__ __forceinline__ void frag_au(uint32_t* a, const uint32_t* S, int SA,
                                        int r, int kw, int gid, int tig)
{
    const uint32_t* p0 = S + (r + gid) * SA + kw + tig;
    const uint32_t* p1 = S + (r + gid + 8) * SA + kw + tig;
    a[0] = p0[0]; a[1] = p1[0]; a[2] = p0[4]; a[3] = p1[4];
}

// ---------------------------------------------------------------------------
// Tensor-core GEMM, single fp16 product: C = A16 @ B16 + bias.
// (validated R12 — unchanged)
// ---------------------------------------------------------------------------
static constexpr int BA_S = 20;    // A u32 row stride (16 words + pad)
static constexpr int BB_S = 136;   // B u32 kp-row stride (128 words + pad)
static constexpr int GB_BH = 128 * BA_S;              // 2560
static constexpr int G_TOT = (GB_BH + 16 * BB_S) * 4; // 18944 bytes

__global__ __launch_bounds__(256) void gemm_f16(
    const float* __restrict__ A, const float* __restrict__ B,
    const float* __restrict__ bias, float* __restrict__ C,
    int N, int K)
{
    extern __shared__ uint32_t smu[];
    uint32_t* AH = smu;
    uint32_t* BH = smu + GB_BH;

    const int tid = threadIdx.x;
    const int wid = tid >> 5;
    const int lane = tid & 31;
    const int gid = lane >> 2, tig = lane & 3;
    const int wm = (wid >> 1) * 32;   // warp row offset in tile
    const int wn = (wid & 1) * 64;    // warp col offset in tile
    const int row0 = blockIdx.y * 128;
    const int col0 = blockIdx.x * 128;

    // stagers
    const int ar  = tid >> 1;           // 0..127
    const int ak  = (tid & 1) * 16;     // float offset 0 or 16
    const int bkp = tid >> 4;           // 0..15 (k-pair row)
    const int bn0 = (tid & 15) * 8;     // 0..120

    const float* Ap  = A + (size_t)(row0 + ar) * K + ak;
    const float* Bp0 = B + col0 + bn0;

    float c[2][8][4];
    #pragma unroll
    for (int i = 0; i < 2; i++)
        #pragma unroll
        for (int j = 0; j < 8; j++)
            #pragma unroll
            for (int q = 0; q < 4; q++) c[i][j][q] = 0.f;

    for (int kc = 0; kc < K; kc += 32) {
        __syncthreads();
        // ---- stage A (128 x 32 fp32 -> 128 x 16 u32 fp16x2) ----
        #pragma unroll
        for (int i = 0; i < 4; i++) {
            float4 v = *(const float4*)(Ap + kc + i * 4);
            const int w = ar * BA_S + ak / 2 + i * 2;
            AH[w]     = fpack2(v.x, v.y);
            AH[w + 1] = fpack2(v.z, v.w);
        }
        // ---- stage B (32 x 128 fp32 -> 16 kp-rows x 128 u32) ----
        {
            const float* Bp = Bp0 + (size_t)(kc + 2 * bkp) * N;
            float4 x0 = *(const float4*)(Bp);
            float4 x1 = *(const float4*)(Bp + 4);
            float4 y0 = *(const float4*)(Bp + N);
            float4 y1 = *(const float4*)(Bp + N + 4);
            const float xa[8] = {x0.x, x0.y, x0.z, x0.w, x1.x, x1.y, x1.z, x1.w};
            const float ya[8] = {y0.x, y0.y, y0.z, y0.w, y1.x, y1.y, y1.z, y1.w};
            #pragma unroll
            for (int cI = 0; cI < 8; cI++)     // word = (B[k][n], B[k+1][n])
                BH[bkp * BB_S + bn0 + cI] = fpack2(xa[cI], ya[cI]);
        }
        __syncthreads();

        // ---- MMA: 2 x k16 steps, single product ----
        #pragma unroll
        for (int ks = 0; ks < 2; ks++) {
            uint32_t ah[2][4];
            frag_au(ah[0], AH, BA_S, wm,      ks * 8, gid, tig);
            frag_au(ah[1], AH, BA_S, wm + 16, ks * 8, gid, tig);
            #pragma unroll
            for (int j = 0; j < 8; j++) {
                const int base = (ks * 8 + tig) * BB_S + wn + j * 8 + gid;
                uint32_t bh[2];
                bh[0] = BH[base]; bh[1] = BH[base + 4 * BB_S];
                mma_f16(c[0][j], ah[0], bh);
                mma_f16(c[1][j], ah[1], bh);
            }
        }
    }

    // ---- epilogue: c frags + bias -> gmem ----
    #pragma unroll
    for (int i = 0; i < 2; i++) {
        const int r0 = row0 + wm + i * 16 + gid;
        #pragma unroll
        for (int j = 0; j < 8; j++) {
            const int col = col0 + wn + j * 8 + 2 * tig;
            float2 bv = *(const float2*)&bias[col];
            float2 o0 = make_float2(c[i][j][0] + bv.x, c[i][j][1] + bv.y);
            float2 o1 = make_float2(c[i][j][2] + bv.x, c[i][j][3] + bv.y);
            *(float2*)&C[(size_t)r0 * N + col]       = o0;
            *(float2*)&C[(size_t)(r0 + 8) * N + col] = o1;
        }
    }
}

// ---------------------------------------------------------------------------
// k_mean — widened to 1024 threads (16-way t split) for latency hiding.
// ---------------------------------------------------------------------------
__global__ __launch_bounds__(1024) void kmean_kernel()
{
    const int bh = blockIdx.x;
    const int b = bh >> 4, h = bh & 15;
    const int c  = threadIdx.x & 63;
    const int tg = threadIdx.x >> 6;   // 0..15
    const float* base = g_qkv + (size_t)b * T_SEQ * W3 + h * 192 + CH + c;
    float s = 0.f;
    for (int t = tg; t < T_SEQ; t += 16) s += base[(size_t)t * W3];
    __shared__ float red[16][64];
    red[tg][c] = s;
    __syncthreads();
    if (tg == 0) {
        float tot = 0.f;
        #pragma unroll
        for (int w = 0; w < 16; w++) tot += red[w][c];
        g_kmean[bh * CH + c] = tot * (1.f / (float)T_SEQ);
    }
}

// ---------------------------------------------------------------------------
// pos — one warp per row, pure shuffle reduce. grid = MROWS/8, 256 threads.
// ---------------------------------------------------------------------------
__global__ __launch_bounds__(256) void pos_kernel()
{
    const int w = threadIdx.x >> 5, lane = threadIdx.x & 31;
    const int bt = blockIdx.x * 8 + w;
    const int b  = bt >> 11;
    const float* qb = g_qkv + (size_t)bt * W3;
    const float* km = g_kmean + b * WID;
    float s = 0.f;
    #pragma unroll 8
    for (int i = 0; i < 32; i++) {
        const int j = lane + 32 * i;
        const int h = j >> 6, c = j & 63;
        s += qb[h * 192 + c] * km[j];
    }
    #pragma unroll
    for (int msk = 16; msk; msk >>= 1) s += __shfl_xor_sync(0xffffffffu, s, msk);
    if (lane == 0) g_pos[bt] = s * 0.125f;
}

// ---------------------------------------------------------------------------
// aw — unchanged
// ---------------------------------------------------------------------------
__global__ __launch_bounds__(256) void aw_kernel()
{
    const int b = blockIdx.x;
    const int tid = threadIdx.x;
    float vals[8];
    float mn = 1e30f, mx = -1e30f;
    #pragma unroll
    for (int k = 0; k < 8; k++) {
        float v = g_pos[b * T_SEQ + tid + 256 * k];
        vals[k] = v;
        mn = fminf(mn, v);
        mx = fmaxf(mx, v);
    }
    __shared__ float smn[256], smx[256];
    smn[tid] = mn; smx[tid] = mx;
    __syncthreads();
    for (int s = 128; s; s >>= 1) {
        if (tid < s) {
            smn[tid] = fminf(smn[tid], smn[tid + s]);
            smx[tid] = fmaxf(smx[tid], smx[tid + s]);
        }
        __syncthreads();
    }
    const float gmn = smn[0];
    const float inv = 1.f / (smx[0] - smn[0] + 1e-6f);
    #pragma unroll
    for (int k = 0; k < 8; k++)
        g_aw[b * T_SEQ + tid + 256 * k] = (vals[k] - gmn) * inv;
}

// ---------------------------------------------------------------------------
// Flash attention — single fp16, m16n8k16, P in registers.
// NEW: 128-key staging per sync pair (two 64-key buffer pairs) — halves
// barrier count (64 -> 32 per CTA) and loop overhead. Values identical.
// Smem 55296 B. 256 threads / 8 warps, Q-tile 128. 2 CTAs/SM.
// ---------------------------------------------------------------------------
static constexpr int FQS = 36;   // Q/K u32 row stride
static constexpr int FVS = 72;   // V u32 row stride
static constexpr int U_QH = 0;
static constexpr int U_K0 = 128 * FQS;          // 4608
static constexpr int U_K1 = U_K0 + 64 * FQS;    // 6912
static constexpr int U_V0 = U_K1 + 64 * FQS;    // 9216
static constexpr int U_V1 = U_V0 + 32 * FVS;    // 11520
static constexpr int FA_TOT = (U_V1 + 32 * FVS) * 4;  // 55296 bytes

__global__ __launch_bounds__(256, 2) void flash_attn_tc()
{
    extern __shared__ uint32_t smu[];
    uint32_t* QH = smu + U_QH;

    const int tid = threadIdx.x;
    const int wid = tid >> 5;
    const int lane = tid & 31;
    const int gid = lane >> 2, tig = lane & 3;
    const int bh  = blockIdx.y;
    const int b = bh >> 4, h = bh & 15;
    const int q0 = blockIdx.x * 128;
    const float* base = g_qkv + (size_t)b * T_SEQ * W3 + h * 192;

    // ---- Load Q tile (128 rows): prescale 1/8, single fp16, pack pairs ----
    {
        const int r = tid >> 1, c0 = (tid & 1) * 32;
        const float* qrow = base + (size_t)(q0 + r) * W3 + c0;
        #pragma unroll
        for (int i = 0; i < 8; i++) {
            float4 v = *(const float4*)(qrow + i * 4);
            const int w = r * FQS + c0 / 2 + i * 2;
            QH[w]     = fpack2(v.x * 0.125f, v.y * 0.125f);
            QH[w + 1] = fpack2(v.z * 0.125f, v.w * 0.125f);
        }
    }

    const int wq = wid * 16;   // warp's q-row offset within tile

    float m0 = -1e30f, m1 = -1e30f, l0v = 0.f, l1v = 0.f;
    float O[8][4];
    #pragma unroll
    for (int j = 0; j < 8; j++)
        #pragma unroll
        for (int q = 0; q < 4; q++) O[j][q] = 0.f;

    // 64-key compute block (S -> online softmax -> PV), identical math to R12.
    auto chunk = [&](const uint32_t* KH, const uint32_t* VH) {
        float s[8][4];
        #pragma unroll
        for (int j = 0; j < 8; j++)
            #pragma unroll
            for (int q = 0; q < 4; q++) s[j][q] = 0.f;
        #pragma unroll
        for (int ks = 0; ks < 4; ks++) {          // 4 x k16 over 64 channels
            uint32_t ah[4];
            frag_au(ah, QH, FQS, wq, ks * 8, gid, tig);
            #pragma unroll
            for (int j = 0; j < 8; j++) {
                const int krow = (j * 8 + gid) * FQS + ks * 8 + tig;
                uint32_t bh_[2];
                bh_[0] = KH[krow]; bh_[1] = KH[krow + 4];
                mma_f16(s[j], ah, bh_);
            }
        }

        float mx0 = -1e30f, mx1 = -1e30f;
        #pragma unroll
        for (int j = 0; j < 8; j++) {
            mx0 = fmaxf(mx0, fmaxf(s[j][0], s[j][1]));
            mx1 = fmaxf(mx1, fmaxf(s[j][2], s[j][3]));
        }
        #pragma unroll
        for (int msk = 1; msk < 4; msk <<= 1) {
            mx0 = fmaxf(mx0, __shfl_xor_sync(0xffffffffu, mx0, msk));
            mx1 = fmaxf(mx1, __shfl_xor_sync(0xffffffffu, mx1, msk));
        }
        const float mn0 = fmaxf(m0, mx0), mn1 = fmaxf(m1, mx1);
        const float al0 = __expf(m0 - mn0), al1 = __expf(m1 - mn1);
        m0 = mn0; m1 = mn1;
        float sum0 = 0.f, sum1 = 0.f;
        #pragma unroll
        for (int j = 0; j < 8; j++) {
            s[j][0] = __expf(s[j][0] - mn0); sum0 += s[j][0];
            s[j][1] = __expf(s[j][1] - mn0); sum0 += s[j][1];
            s[j][2] = __expf(s[j][2] - mn1); sum1 += s[j][2];
            s[j][3] = __expf(s[j][3] - mn1); sum1 += s[j][3];
        }
        #pragma unroll
        for (int msk = 1; msk < 4; msk <<= 1) {
            sum0 += __shfl_xor_sync(0xffffffffu, sum0, msk);
            sum1 += __shfl_xor_sync(0xffffffffu, sum1, msk);
        }
        l0v = l0v * al0 + sum0;
        l1v = l1v * al1 + sum1;
        #pragma unroll
        for (int j = 0; j < 8; j++) {
            O[j][0] *= al0; O[j][1] *= al0;
            O[j][2] *= al1; O[j][3] *= al1;
        }

        #pragma unroll
        for (int kt = 0; kt < 4; kt++) {
            uint32_t ph[4];
            ph[0] = fpack2(s[2 * kt][0],     s[2 * kt][1]);
            ph[1] = fpack2(s[2 * kt][2],     s[2 * kt][3]);
            ph[2] = fpack2(s[2 * kt + 1][0], s[2 * kt + 1][1]);
            ph[3] = fpack2(s[2 * kt + 1][2], s[2 * kt + 1][3]);
            #pragma unroll
            for (int j = 0; j < 8; j++) {
                const int vrow = (kt * 8 + tig) * FVS + j * 8 + gid;
                uint32_t vh_[2];
                vh_[0] = VH[vrow]; vh_[1] = VH[vrow + 4 * FVS];
                mma_f16(O[j], ph, vh_);
            }
        }
    };

    for (int t0 = 0; t0 < T_SEQ; t0 += 128) {
        __syncthreads();   // all warps done with previous K/V buffers
        // ---- stage K for both 64-key sub-chunks ----
        {
            const int r = tid >> 2, c0 = (tid & 3) * 16;
            const float* kr0 = base + (size_t)(t0 + r) * W3 + CH + c0;
            const float* kr1 = kr0 + (size_t)64 * W3;
            #pragma unroll
            for (int i = 0; i < 4; i++) {
                float4 v = *(const float4*)(kr0 + i * 4);
                const int w = r * FQS + c0 / 2 + i * 2;
                smu[U_K0 + w]     = fpack2(v.x, v.y);
                smu[U_K0 + w + 1] = fpack2(v.z, v.w);
                float4 u = *(const float4*)(kr1 + i * 4);
                smu[U_K1 + w]     = fpack2(u.x, u.y);
                smu[U_K1 + w + 1] = fpack2(u.z, u.w);
            }
        }
        // ---- stage V for both sub-chunks: word = (V[2kp][c], V[2kp+1][c]) ----
        {
            const int kp = tid >> 3, c0 = (tid & 7) * 8;
            #pragma unroll
            for (int half = 0; half < 2; half++) {
                const float* v0 = base + (size_t)(t0 + half * 64 + 2 * kp) * W3
                                  + 2 * CH + c0;
                const float* v1 = v0 + W3;
                float4 a0 = *(const float4*)(v0);
                float4 a1 = *(const float4*)(v0 + 4);
                float4 b0 = *(const float4*)(v1);
                float4 b1 = *(const float4*)(v1 + 4);
                const float va[8] = {a0.x, a0.y, a0.z, a0.w,
                                     a1.x, a1.y, a1.z, a1.w};
                const float vb[8] = {b0.x, b0.y, b0.z, b0.w,
                                     b1.x, b1.y, b1.z, b1.w};
                const int vbase = (half ? U_V1 : U_V0) + kp * FVS + c0;
                #pragma unroll
                for (int c = 0; c < 8; c++)
                    smu[vbase + c] = fpack2(va[c], vb[c]);
            }
        }
        __syncthreads();

        chunk(smu + U_K0, smu + U_V0);
        chunk(smu + U_K1, smu + U_V1);
    }

    // ---- epilogue: normalize, apply adaptive weight, write g_attn ----
    const int t0r = q0 + wq + gid;
    const int t1r = t0r + 8;
    const float w0 = g_aw[b * T_SEQ + t0r] / l0v;
    const float w1 = g_aw[b * T_SEQ + t1r] / l1v;
    float* o0 = g_attn + (size_t)(b * T_SEQ + t0r) * WID + h * CH;
    float* o1 = g_attn + (size_t)(b * T_SEQ + t1r) * WID + h * CH;
    #pragma unroll
    for (int j = 0; j < 8; j++) {
        const int cc = j * 8 + 2 * tig;
        *(float2*)(o0 + cc) = make_float2(O[j][0] * w0, O[j][1] * w0);
        *(float2*)(o1 + cc) = make_float2(O[j][2] * w1, O[j][3] * w1);
    }
}

// ---------------------------------------------------------------------------
extern "C" void kernel_launch(void* const* d_in, const int* in_sizes, int n_in,
                              void* d_out, int out_size)
{
    const float* x     = (const float*)d_in[0];
    const float* Wqkv  = (const float*)d_in[1];
    const float* bqkv  = (const float*)d_in[2];
    const float* Wproj = (const float*)d_in[3];
    const float* bproj = (const float*)d_in[4];
    float* out = (float*)d_out;

    float *qkv, *attn;
    cudaGetSymbolAddress((void**)&qkv,  g_qkv);
    cudaGetSymbolAddress((void**)&attn, g_attn);

    static bool attr_set = false;
    if (!attr_set) {
        cudaFuncSetAttribute(gemm_f16, cudaFuncAttributeMaxDynamicSharedMemorySize, G_TOT);
        cudaFuncSetAttribute(flash_attn_tc, cudaFuncAttributeMaxDynamicSharedMemorySize, FA_TOT);
        attr_set = true;
    }

    // 1) qkv = x @ W_qkv + b_qkv       (tensor, single fp16)
    gemm_f16<<<dim3(W3 / 128, MROWS / 128), 256, G_TOT>>>(x, Wqkv, bqkv, qkv, W3, WID);
    // 2) k_mean  (1024-thread blocks)
    kmean_kernel<<<BATCH * HEADS, 1024>>>();
    // 3) pos = (q . k_mean)/8  (warp per row)
    pos_kernel<<<MROWS / 8, 256>>>();
    // 4) adaptive weight
    aw_kernel<<<BATCH, 256>>>();
    // 5) attention (tensor, single fp16, 128-key staging; applies aw)
    flash_attn_tc<<<dim3(T_SEQ / 128, BH_N), 256, FA_TOT>>>();
    // 6) out = attn @ W_proj + b_proj  (tensor, single fp16)
    gemm_f16<<<dim3(WID / 128, MROWS / 128), 256, G_TOT>>>(attn, Wproj, bproj, out, WID, WID);
}

// round 14
// speedup vs baseline: 1.7726x; 1.0298x over previous
#include <cuda_runtime.h>
#include <cuda_fp16.h>
#include <cstdint>

// Problem constants
#define BATCH  2
#define T_SEQ  2048
#define WID    1024
#define HEADS  16
#define CH     64
#define W3     3072
#define MROWS  (BATCH * T_SEQ)   // 4096
#define BH_N   (BATCH * HEADS)   // 32

// Scratch (allocation-free rule: use __device__ globals)
__device__ float g_qkv [BATCH * T_SEQ * W3];    // 48 MB
__device__ float g_attn[BATCH * T_SEQ * WID];   // 16 MB
__device__ float g_kmean[BATCH * HEADS * CH];
__device__ float g_pos [BATCH * T_SEQ];
__device__ float g_aw  [BATCH * T_SEQ];

// ---------------------------------------------------------------------------
// mma.sync helpers (plain PTX — legal in compute_103 PTX)
// ---------------------------------------------------------------------------
__device__ __forceinline__ void mma_f16(float* c, const uint32_t* a, const uint32_t* b)
{
    asm volatile(
        "mma.sync.aligned.m16n8k16.row.col.f32.f16.f16.f32 "
        "{%0,%1,%2,%3}, {%4,%5,%6,%7}, {%8,%9}, {%0,%1,%2,%3};"
        : "+f"(c[0]), "+f"(c[1]), "+f"(c[2]), "+f"(c[3])
        : "r"(a[0]), "r"(a[1]), "r"(a[2]), "r"(a[3]),
          "r"(b[0]), "r"(b[1]));
}

// Pack two fp32 into one fp16x2 word (low half = first value).
__device__ __forceinline__ uint32_t fpack2(float x0, float x1)
{
    __half h0 = __float2half_rn(x0);
    __half h1 = __float2half_rn(x1);
    return (uint32_t)__half_as_ushort(h0) |
           ((uint32_t)__half_as_ushort(h1) << 16);
}

// u32-packed A-frag (m16k16). lane = gid*4+tig; kw = k-word offset (k/2).
__device__ __forceinline__ void frag_au(uint32_t* a, const uint32_t* S, int SA,
                                        int r, int kw, int gid, int tig)
{
    const uint32_t* p0 = S + (r + gid) * SA + kw + tig;
    const uint32_t* p1 = S + (r + gid + 8) * SA + kw + tig;
    a[0] = p0[0]; a[1] = p1[0]; a[2] = p0[4]; a[3] = p1[4];
}

// ---------------------------------------------------------------------------
// Tensor-core GEMM, single fp16 product: C = A16 @ B16 + bias.
// NEW vs R13: K-chunk 64 (two 32-wide sub-buffers per sync pair) — halves
// barrier count (64 -> 32 per CTA), doubles MMA run between barriers.
// Values bit-identical. Smem 37888 B.
// ---------------------------------------------------------------------------
static constexpr int BA_S = 20;    // A u32 row stride (16 words + pad)
static constexpr int BB_S = 136;   // B u32 kp-row stride (128 words + pad)
static constexpr int GA_SZ = 128 * BA_S;              // 2560 u32 per A buf
static constexpr int GB_SZ = 16 * BB_S;               // 2176 u32 per B buf
static constexpr int GB_B0 = 2 * GA_SZ;               // 5120
static constexpr int G_TOT = (GB_B0 + 2 * GB_SZ) * 4; // 37888 bytes

__global__ __launch_bounds__(256) void gemm_f16(
    const float* __restrict__ A, const float* __restrict__ B,
    const float* __restrict__ bias, float* __restrict__ C,
    int N, int K)
{
    extern __shared__ uint32_t smu[];

    const int tid = threadIdx.x;
    const int wid = tid >> 5;
    const int lane = tid & 31;
    const int gid = lane >> 2, tig = lane & 3;
    const int wm = (wid >> 1) * 32;   // warp row offset in tile
    const int wn = (wid & 1) * 64;    // warp col offset in tile
    const int row0 = blockIdx.y * 128;
    const int col0 = blockIdx.x * 128;

    // stagers
    const int ar  = tid >> 1;           // 0..127
    const int ak  = (tid & 1) * 16;     // float offset 0 or 16
    const int bkp = tid >> 4;           // 0..15 (k-pair row)
    const int bn0 = (tid & 15) * 8;     // 0..120

    const float* Ap  = A + (size_t)(row0 + ar) * K + ak;
    const float* Bp0 = B + col0 + bn0;

    float c[2][8][4];
    #pragma unroll
    for (int i = 0; i < 2; i++)
        #pragma unroll
        for (int j = 0; j < 8; j++)
            #pragma unroll
            for (int q = 0; q < 4; q++) c[i][j][q] = 0.f;

    for (int kc = 0; kc < K; kc += 64) {
        __syncthreads();
        // ---- stage A: two 32-wide sub-chunks ----
        #pragma unroll
        for (int sb = 0; sb < 2; sb++) {
            uint32_t* AH = smu + sb * GA_SZ;
            #pragma unroll
            for (int i = 0; i < 4; i++) {
                float4 v = *(const float4*)(Ap + kc + sb * 32 + i * 4);
                const int w = ar * BA_S + ak / 2 + i * 2;
                AH[w]     = fpack2(v.x, v.y);
                AH[w + 1] = fpack2(v.z, v.w);
            }
        }
        // ---- stage B: two 32-wide sub-chunks ----
        #pragma unroll
        for (int sb = 0; sb < 2; sb++) {
            uint32_t* BH = smu + GB_B0 + sb * GB_SZ;
            const float* Bp = Bp0 + (size_t)(kc + sb * 32 + 2 * bkp) * N;
            float4 x0 = *(const float4*)(Bp);
            float4 x1 = *(const float4*)(Bp + 4);
            float4 y0 = *(const float4*)(Bp + N);
            float4 y1 = *(const float4*)(Bp + N + 4);
            const float xa[8] = {x0.x, x0.y, x0.z, x0.w, x1.x, x1.y, x1.z, x1.w};
            const float ya[8] = {y0.x, y0.y, y0.z, y0.w, y1.x, y1.y, y1.z, y1.w};
            #pragma unroll
            for (int cI = 0; cI < 8; cI++)     // word = (B[k][n], B[k+1][n])
                BH[bkp * BB_S + bn0 + cI] = fpack2(xa[cI], ya[cI]);
        }
        __syncthreads();

        // ---- MMA: 2 sub-chunks x 2 k16 steps, single product ----
        #pragma unroll
        for (int sb = 0; sb < 2; sb++) {
            const uint32_t* AH = smu + sb * GA_SZ;
            const uint32_t* BH = smu + GB_B0 + sb * GB_SZ;
            #pragma unroll
            for (int ks = 0; ks < 2; ks++) {
                uint32_t ah[2][4];
                frag_au(ah[0], AH, BA_S, wm,      ks * 8, gid, tig);
                frag_au(ah[1], AH, BA_S, wm + 16, ks * 8, gid, tig);
                #pragma unroll
                for (int j = 0; j < 8; j++) {
                    const int base = (ks * 8 + tig) * BB_S + wn + j * 8 + gid;
                    uint32_t bh[2];
                    bh[0] = BH[base]; bh[1] = BH[base + 4 * BB_S];
                    mma_f16(c[0][j], ah[0], bh);
                    mma_f16(c[1][j], ah[1], bh);
                }
            }
        }
    }

    // ---- epilogue: c frags + bias -> gmem ----
    #pragma unroll
    for (int i = 0; i < 2; i++) {
        const int r0 = row0 + wm + i * 16 + gid;
        #pragma unroll
        for (int j = 0; j < 8; j++) {
            const int col = col0 + wn + j * 8 + 2 * tig;
            float2 bv = *(const float2*)&bias[col];
            float2 o0 = make_float2(c[i][j][0] + bv.x, c[i][j][1] + bv.y);
            float2 o1 = make_float2(c[i][j][2] + bv.x, c[i][j][3] + bv.y);
            *(float2*)&C[(size_t)r0 * N + col]       = o0;
            *(float2*)&C[(size_t)(r0 + 8) * N + col] = o1;
        }
    }
}

// ---------------------------------------------------------------------------
// k_mean — 1024 threads (validated R13)
// ---------------------------------------------------------------------------
__global__ __launch_bounds__(1024) void kmean_kernel()
{
    const int bh = blockIdx.x;
    const int b = bh >> 4, h = bh & 15;
    const int c  = threadIdx.x & 63;
    const int tg = threadIdx.x >> 6;   // 0..15
    const float* base = g_qkv + (size_t)b * T_SEQ * W3 + h * 192 + CH + c;
    float s = 0.f;
    for (int t = tg; t < T_SEQ; t += 16) s += base[(size_t)t * W3];
    __shared__ float red[16][64];
    red[tg][c] = s;
    __syncthreads();
    if (tg == 0) {
        float tot = 0.f;
        #pragma unroll
        for (int w = 0; w < 16; w++) tot += red[w][c];
        g_kmean[bh * CH + c] = tot * (1.f / (float)T_SEQ);
    }
}

// ---------------------------------------------------------------------------
// pos — one warp per row (validated R13)
// ---------------------------------------------------------------------------
__global__ __launch_bounds__(256) void pos_kernel()
{
    const int w = threadIdx.x >> 5, lane = threadIdx.x & 31;
    const int bt = blockIdx.x * 8 + w;
    const int b  = bt >> 11;
    const float* qb = g_qkv + (size_t)bt * W3;
    const float* km = g_kmean + b * WID;
    float s = 0.f;
    #pragma unroll 8
    for (int i = 0; i < 32; i++) {
        const int j = lane + 32 * i;
        const int h = j >> 6, c = j & 63;
        s += qb[h * 192 + c] * km[j];
    }
    #pragma unroll
    for (int msk = 16; msk; msk >>= 1) s += __shfl_xor_sync(0xffffffffu, s, msk);
    if (lane == 0) g_pos[bt] = s * 0.125f;
}

// ---------------------------------------------------------------------------
// aw — unchanged
// ---------------------------------------------------------------------------
__global__ __launch_bounds__(256) void aw_kernel()
{
    const int b = blockIdx.x;
    const int tid = threadIdx.x;
    float vals[8];
    float mn = 1e30f, mx = -1e30f;
    #pragma unroll
    for (int k = 0; k < 8; k++) {
        float v = g_pos[b * T_SEQ + tid + 256 * k];
        vals[k] = v;
        mn = fminf(mn, v);
        mx = fmaxf(mx, v);
    }
    __shared__ float smn[256], smx[256];
    smn[tid] = mn; smx[tid] = mx;
    __syncthreads();
    for (int s = 128; s; s >>= 1) {
        if (tid < s) {
            smn[tid] = fminf(smn[tid], smn[tid + s]);
            smx[tid] = fmaxf(smx[tid], smx[tid + s]);
        }
        __syncthreads();
    }
    const float gmn = smn[0];
    const float inv = 1.f / (smx[0] - smn[0] + 1e-6f);
    #pragma unroll
    for (int k = 0; k < 8; k++)
        g_aw[b * T_SEQ + tid + 256 * k] = (vals[k] - gmn) * inv;
}

// ---------------------------------------------------------------------------
// Flash attention — single fp16, m16n8k16, P in registers.
// NEW vs R13: 256-key staging per sync pair (4x 64-key K/V buffers) —
// halves barrier count (32 -> 16 per CTA). Values bit-identical.
// Smem 92160 B. 256 threads / 8 warps, Q-tile 128. 2 CTAs/SM (184 KB).
// ---------------------------------------------------------------------------
static constexpr int FQS = 36;   // Q/K u32 row stride
static constexpr int FVS = 72;   // V u32 row stride
static constexpr int U_QH = 0;
static constexpr int KBUF = 64 * FQS;           // 2304 u32 per K buf
static constexpr int VBUF = 32 * FVS;           // 2304 u32 per V buf
static constexpr int U_K0 = 128 * FQS;          // 4608
static constexpr int U_V0 = U_K0 + 4 * KBUF;    // 13824
static constexpr int FA_TOT = (U_V0 + 4 * VBUF) * 4;  // 92160 bytes

__global__ __launch_bounds__(256, 2) void flash_attn_tc()
{
    extern __shared__ uint32_t smu[];
    uint32_t* QH = smu + U_QH;

    const int tid = threadIdx.x;
    const int wid = tid >> 5;
    const int lane = tid & 31;
    const int gid = lane >> 2, tig = lane & 3;
    const int bh  = blockIdx.y;
    const int b = bh >> 4, h = bh & 15;
    const int q0 = blockIdx.x * 128;
    const float* base = g_qkv + (size_t)b * T_SEQ * W3 + h * 192;

    // ---- Load Q tile (128 rows): prescale 1/8, single fp16, pack pairs ----
    {
        const int r = tid >> 1, c0 = (tid & 1) * 32;
        const float* qrow = base + (size_t)(q0 + r) * W3 + c0;
        #pragma unroll
        for (int i = 0; i < 8; i++) {
            float4 v = *(const float4*)(qrow + i * 4);
            const int w = r * FQS + c0 / 2 + i * 2;
            QH[w]     = fpack2(v.x * 0.125f, v.y * 0.125f);
            QH[w + 1] = fpack2(v.z * 0.125f, v.w * 0.125f);
        }
    }

    const int wq = wid * 16;   // warp's q-row offset within tile

    float m0 = -1e30f, m1 = -1e30f, l0v = 0.f, l1v = 0.f;
    float O[8][4];
    #pragma unroll
    for (int j = 0; j < 8; j++)
        #pragma unroll
        for (int q = 0; q < 4; q++) O[j][q] = 0.f;

    // 64-key compute block (S -> online softmax -> PV), identical math.
    auto chunk = [&](const uint32_t* KH, const uint32_t* VH) {
        float s[8][4];
        #pragma unroll
        for (int j = 0; j < 8; j++)
            #pragma unroll
            for (int q = 0; q < 4; q++) s[j][q] = 0.f;
        #pragma unroll
        for (int ks = 0; ks < 4; ks++) {          // 4 x k16 over 64 channels
            uint32_t ah[4];
            frag_au(ah, QH, FQS, wq, ks * 8, gid, tig);
            #pragma unroll
            for (int j = 0; j < 8; j++) {
                const int krow = (j * 8 + gid) * FQS + ks * 8 + tig;
                uint32_t bh_[2];
                bh_[0] = KH[krow]; bh_[1] = KH[krow + 4];
                mma_f16(s[j], ah, bh_);
            }
        }

        float mx0 = -1e30f, mx1 = -1e30f;
        #pragma unroll
        for (int j = 0; j < 8; j++) {
            mx0 = fmaxf(mx0, fmaxf(s[j][0], s[j][1]));
            mx1 = fmaxf(mx1, fmaxf(s[j][2], s[j][3]));
        }
        #pragma unroll
        for (int msk = 1; msk < 4; msk <<= 1) {
            mx0 = fmaxf(mx0, __shfl_xor_sync(0xffffffffu, mx0, msk));
            mx1 = fmaxf(mx1, __shfl_xor_sync(0xffffffffu, mx1, msk));
        }
        const float mn0 = fmaxf(m0, mx0), mn1 = fmaxf(m1, mx1);
        const float al0 = __expf(m0 - mn0), al1 = __expf(m1 - mn1);
        m0 = mn0; m1 = mn1;
        float sum0 = 0.f, sum1 = 0.f;
        #pragma unroll
        for (int j = 0; j < 8; j++) {
            s[j][0] = __expf(s[j][0] - mn0); sum0 += s[j][0];
            s[j][1] = __expf(s[j][1] - mn0); sum0 += s[j][1];
            s[j][2] = __expf(s[j][2] - mn1); sum1 += s[j][2];
            s[j][3] = __expf(s[j][3] - mn1); sum1 += s[j][3];
        }
        #pragma unroll
        for (int msk = 1; msk < 4; msk <<= 1) {
            sum0 += __shfl_xor_sync(0xffffffffu, sum0, msk);
            sum1 += __shfl_xor_sync(0xffffffffu, sum1, msk);
        }
        l0v = l0v * al0 + sum0;
        l1v = l1v * al1 + sum1;
        #pragma unroll
        for (int j = 0; j < 8; j++) {
            O[j][0] *= al0; O[j][1] *= al0;
            O[j][2] *= al1; O[j][3] *= al1;
        }

        #pragma unroll
        for (int kt = 0; kt < 4; kt++) {
            uint32_t ph[4];
            ph[0] = fpack2(s[2 * kt][0],     s[2 * kt][1]);
            ph[1] = fpack2(s[2 * kt][2],     s[2 * kt][3]);
            ph[2] = fpack2(s[2 * kt + 1][0], s[2 * kt + 1][1]);
            ph[3] = fpack2(s[2 * kt + 1][2], s[2 * kt + 1][3]);
            #pragma unroll
            for (int j = 0; j < 8; j++) {
                const int vrow = (kt * 8 + tig) * FVS + j * 8 + gid;
                uint32_t vh_[2];
                vh_[0] = VH[vrow]; vh_[1] = VH[vrow + 4 * FVS];
                mma_f16(O[j], ph, vh_);
            }
        }
    };

    for (int t0 = 0; t0 < T_SEQ; t0 += 256) {
        __syncthreads();   // all warps done with previous K/V buffers
        // ---- stage K for 4 x 64-key sub-chunks ----
        {
            const int r = tid >> 2, c0 = (tid & 3) * 16;
            #pragma unroll
            for (int half = 0; half < 4; half++) {
                const float* kr = base + (size_t)(t0 + half * 64 + r) * W3
                                  + CH + c0;
                uint32_t* KH = smu + U_K0 + half * KBUF;
                #pragma unroll
                for (int i = 0; i < 4; i++) {
                    float4 v = *(const float4*)(kr + i * 4);
                    const int w = r * FQS + c0 / 2 + i * 2;
                    KH[w]     = fpack2(v.x, v.y);
                    KH[w + 1] = fpack2(v.z, v.w);
                }
            }
        }
        // ---- stage V for 4 sub-chunks: word = (V[2kp][c], V[2kp+1][c]) ----
        {
            const int kp = tid >> 3, c0 = (tid & 7) * 8;
            #pragma unroll
            for (int half = 0; half < 4; half++) {
                const float* v0 = base + (size_t)(t0 + half * 64 + 2 * kp) * W3
                                  + 2 * CH + c0;
                const float* v1 = v0 + W3;
                float4 a0 = *(const float4*)(v0);
                float4 a1 = *(const float4*)(v0 + 4);
                float4 b0 = *(const float4*)(v1);
                float4 b1 = *(const float4*)(v1 + 4);
                const float va[8] = {a0.x, a0.y, a0.z, a0.w,
                                     a1.x, a1.y, a1.z, a1.w};
                const float vb[8] = {b0.x, b0.y, b0.z, b0.w,
                                     b1.x, b1.y, b1.z, b1.w};
                uint32_t* VH = smu + U_V0 + half * VBUF;
                #pragma unroll
                for (int c = 0; c < 8; c++)
                    VH[kp * FVS + c0 + c] = fpack2(va[c], vb[c]);
            }
        }
        __syncthreads();

        #pragma unroll
        for (int half = 0; half < 4; half++)
            chunk(smu + U_K0 + half * KBUF, smu + U_V0 + half * VBUF);
    }

    // ---- epilogue: normalize, apply adaptive weight, write g_attn ----
    const int t0r = q0 + wq + gid;
    const int t1r = t0r + 8;
    const float w0 = g_aw[b * T_SEQ + t0r] / l0v;
    const float w1 = g_aw[b * T_SEQ + t1r] / l1v;
    float* o0 = g_attn + (size_t)(b * T_SEQ + t0r) * WID + h * CH;
    float* o1 = g_attn + (size_t)(b * T_SEQ + t1r) * WID + h * CH;
    #pragma unroll
    for (int j = 0; j < 8; j++) {
        const int cc = j * 8 + 2 * tig;
        *(float2*)(o0 + cc) = make_float2(O[j][0] * w0, O[j][1] * w0);
        *(float2*)(o1 + cc) = make_float2(O[j][2] * w1, O[j][3] * w1);
    }
}

// ---------------------------------------------------------------------------
extern "C" void kernel_launch(void* const* d_in, const int* in_sizes, int n_in,
                              void* d_out, int out_size)
{
    const float* x     = (const float*)d_in[0];
    const float* Wqkv  = (const float*)d_in[1];
    const float* bqkv  = (const float*)d_in[2];
    const float* Wproj = (const float*)d_in[3];
    const float* bproj = (const float*)d_in[4];
    float* out = (float*)d_out;

    float *qkv, *attn;
    cudaGetSymbolAddress((void**)&qkv,  g_qkv);
    cudaGetSymbolAddress((void**)&attn, g_attn);

    static bool attr_set = false;
    if (!attr_set) {
        cudaFuncSetAttribute(gemm_f16, cudaFuncAttributeMaxDynamicSharedMemorySize, G_TOT);
        cudaFuncSetAttribute(flash_attn_tc, cudaFuncAttributeMaxDynamicSharedMemorySize, FA_TOT);
        attr_set = true;
    }

    // 1) qkv = x @ W_qkv + b_qkv       (tensor, single fp16, K-chunk 64)
    gemm_f16<<<dim3(W3 / 128, MROWS / 128), 256, G_TOT>>>(x, Wqkv, bqkv, qkv, W3, WID);
    // 2) k_mean  (1024-thread blocks)
    kmean_kernel<<<BATCH * HEADS, 1024>>>();
    // 3) pos = (q . k_mean)/8  (warp per row)
    pos_kernel<<<MROWS / 8, 256>>>();
    // 4) adaptive weight
    aw_kernel<<<BATCH, 256>>>();
    // 5) attention (tensor, single fp16, 256-key staging; applies aw)
    flash_attn_tc<<<dim3(T_SEQ / 128, BH_N), 256, FA_TOT>>>();
    // 6) out = attn @ W_proj + b_proj  (tensor, single fp16, K-chunk 64)
    gemm_f16<<<dim3(WID / 128, MROWS / 128), 256, G_TOT>>>(attn, Wproj, bproj, out, WID, WID);
}

// round 15
// speedup vs baseline: 1.8382x; 1.0370x over previous
#include <cuda_runtime.h>
#include <cuda_fp16.h>
#include <cstdint>

// Problem constants
#define BATCH  2
#define T_SEQ  2048
#define WID    1024
#define HEADS  16
#define CH     64
#define W3     3072
#define MROWS  (BATCH * T_SEQ)   // 4096
#define BH_N   (BATCH * HEADS)   // 32

// Scratch (allocation-free rule: use __device__ globals)
__device__ float g_qkv [BATCH * T_SEQ * W3];    // 48 MB
__device__ float g_attn[BATCH * T_SEQ * WID];   // 16 MB
__device__ float g_kmean[BATCH * HEADS * CH];
__device__ float g_pos [BATCH * T_SEQ];
__device__ float g_aw  [BATCH * T_SEQ];

// ---------------------------------------------------------------------------
// mma.sync helpers (plain PTX — legal in compute_103 PTX)
// ---------------------------------------------------------------------------
__device__ __forceinline__ void mma_f16(float* c, const uint32_t* a, const uint32_t* b)
{
    asm volatile(
        "mma.sync.aligned.m16n8k16.row.col.f32.f16.f16.f32 "
        "{%0,%1,%2,%3}, {%4,%5,%6,%7}, {%8,%9}, {%0,%1,%2,%3};"
        : "+f"(c[0]), "+f"(c[1]), "+f"(c[2]), "+f"(c[3])
        : "r"(a[0]), "r"(a[1]), "r"(a[2]), "r"(a[3]),
          "r"(b[0]), "r"(b[1]));
}

// Pack two fp32 into one fp16x2 word (low half = first value) —
// single-instruction cvt.rn.f16x2.f32 (identical rn rounding to the
// two-convert version; just fewer instructions).
__device__ __forceinline__ uint32_t fpack2(float x0, float x1)
{
    uint32_t r;
    asm("cvt.rn.f16x2.f32 %0, %1, %2;" : "=r"(r) : "f"(x1), "f"(x0));
    return r;
}

// u32-packed A-frag (m16k16). lane = gid*4+tig; kw = k-word offset (k/2).
__device__ __forceinline__ void frag_au(uint32_t* a, const uint32_t* S, int SA,
                                        int r, int kw, int gid, int tig)
{
    const uint32_t* p0 = S + (r + gid) * SA + kw + tig;
    const uint32_t* p1 = S + (r + gid + 8) * SA + kw + tig;
    a[0] = p0[0]; a[1] = p1[0]; a[2] = p0[4]; a[3] = p1[4];
}

// ---------------------------------------------------------------------------
// Tensor-core GEMM, single fp16 product: C = A16 @ B16 + bias.
// K-chunk 64 (validated R14). Smem 37888 B.
// ---------------------------------------------------------------------------
static constexpr int BA_S = 20;    // A u32 row stride (16 words + pad)
static constexpr int BB_S = 136;   // B u32 kp-row stride (128 words + pad)
static constexpr int GA_SZ = 128 * BA_S;              // 2560 u32 per A buf
static constexpr int GB_SZ = 16 * BB_S;               // 2176 u32 per B buf
static constexpr int GB_B0 = 2 * GA_SZ;               // 5120
static constexpr int G_TOT = (GB_B0 + 2 * GB_SZ) * 4; // 37888 bytes

__global__ __launch_bounds__(256) void gemm_f16(
    const float* __restrict__ A, const float* __restrict__ B,
    const float* __restrict__ bias, float* __restrict__ C,
    int N, int K)
{
    extern __shared__ uint32_t smu[];

    const int tid = threadIdx.x;
    const int wid = tid >> 5;
    const int lane = tid & 31;
    const int gid = lane >> 2, tig = lane & 3;
    const int wm = (wid >> 1) * 32;   // warp row offset in tile
    const int wn = (wid & 1) * 64;    // warp col offset in tile
    const int row0 = blockIdx.y * 128;
    const int col0 = blockIdx.x * 128;

    // stagers
    const int ar  = tid >> 1;           // 0..127
    const int ak  = (tid & 1) * 16;     // float offset 0 or 16
    const int bkp = tid >> 4;           // 0..15 (k-pair row)
    const int bn0 = (tid & 15) * 8;     // 0..120

    const float* Ap  = A + (size_t)(row0 + ar) * K + ak;
    const float* Bp0 = B + col0 + bn0;

    float c[2][8][4];
    #pragma unroll
    for (int i = 0; i < 2; i++)
        #pragma unroll
        for (int j = 0; j < 8; j++)
            #pragma unroll
            for (int q = 0; q < 4; q++) c[i][j][q] = 0.f;

    for (int kc = 0; kc < K; kc += 64) {
        __syncthreads();
        // ---- stage A: two 32-wide sub-chunks ----
        #pragma unroll
        for (int sb = 0; sb < 2; sb++) {
            uint32_t* AH = smu + sb * GA_SZ;
            #pragma unroll
            for (int i = 0; i < 4; i++) {
                float4 v = *(const float4*)(Ap + kc + sb * 32 + i * 4);
                const int w = ar * BA_S + ak / 2 + i * 2;
                AH[w]     = fpack2(v.x, v.y);
                AH[w + 1] = fpack2(v.z, v.w);
            }
        }
        // ---- stage B: two 32-wide sub-chunks ----
        #pragma unroll
        for (int sb = 0; sb < 2; sb++) {
            uint32_t* BH = smu + GB_B0 + sb * GB_SZ;
            const float* Bp = Bp0 + (size_t)(kc + sb * 32 + 2 * bkp) * N;
            float4 x0 = *(const float4*)(Bp);
            float4 x1 = *(const float4*)(Bp + 4);
            float4 y0 = *(const float4*)(Bp + N);
            float4 y1 = *(const float4*)(Bp + N + 4);
            const float xa[8] = {x0.x, x0.y, x0.z, x0.w, x1.x, x1.y, x1.z, x1.w};
            const float ya[8] = {y0.x, y0.y, y0.z, y0.w, y1.x, y1.y, y1.z, y1.w};
            #pragma unroll
            for (int cI = 0; cI < 8; cI++)     // word = (B[k][n], B[k+1][n])
                BH[bkp * BB_S + bn0 + cI] = fpack2(xa[cI], ya[cI]);
        }
        __syncthreads();

        // ---- MMA: 2 sub-chunks x 2 k16 steps, single product ----
        #pragma unroll
        for (int sb = 0; sb < 2; sb++) {
            const uint32_t* AH = smu + sb * GA_SZ;
            const uint32_t* BH = smu + GB_B0 + sb * GB_SZ;
            #pragma unroll
            for (int ks = 0; ks < 2; ks++) {
                uint32_t ah[2][4];
                frag_au(ah[0], AH, BA_S, wm,      ks * 8, gid, tig);
                frag_au(ah[1], AH, BA_S, wm + 16, ks * 8, gid, tig);
                #pragma unroll
                for (int j = 0; j < 8; j++) {
                    const int base = (ks * 8 + tig) * BB_S + wn + j * 8 + gid;
                    uint32_t bh[2];
                    bh[0] = BH[base]; bh[1] = BH[base + 4 * BB_S];
                    mma_f16(c[0][j], ah[0], bh);
                    mma_f16(c[1][j], ah[1], bh);
                }
            }
        }
    }

    // ---- epilogue: c frags + bias -> gmem ----
    #pragma unroll
    for (int i = 0; i < 2; i++) {
        const int r0 = row0 + wm + i * 16 + gid;
        #pragma unroll
        for (int j = 0; j < 8; j++) {
            const int col = col0 + wn + j * 8 + 2 * tig;
            float2 bv = *(const float2*)&bias[col];
            float2 o0 = make_float2(c[i][j][0] + bv.x, c[i][j][1] + bv.y);
            float2 o1 = make_float2(c[i][j][2] + bv.x, c[i][j][3] + bv.y);
            *(float2*)&C[(size_t)r0 * N + col]       = o0;
            *(float2*)&C[(size_t)(r0 + 8) * N + col] = o1;
        }
    }
}

// ---------------------------------------------------------------------------
// k_mean — 1024 threads (validated R13)
// ---------------------------------------------------------------------------
__global__ __launch_bounds__(1024) void kmean_kernel()
{
    const int bh = blockIdx.x;
    const int b = bh >> 4, h = bh & 15;
    const int c  = threadIdx.x & 63;
    const int tg = threadIdx.x >> 6;   // 0..15
    const float* base = g_qkv + (size_t)b * T_SEQ * W3 + h * 192 + CH + c;
    float s = 0.f;
    for (int t = tg; t < T_SEQ; t += 16) s += base[(size_t)t * W3];
    __shared__ float red[16][64];
    red[tg][c] = s;
    __syncthreads();
    if (tg == 0) {
        float tot = 0.f;
        #pragma unroll
        for (int w = 0; w < 16; w++) tot += red[w][c];
        g_kmean[bh * CH + c] = tot * (1.f / (float)T_SEQ);
    }
}

// ---------------------------------------------------------------------------
// pos — one warp per row (validated R13)
// ---------------------------------------------------------------------------
__global__ __launch_bounds__(256) void pos_kernel()
{
    const int w = threadIdx.x >> 5, lane = threadIdx.x & 31;
    const int bt = blockIdx.x * 8 + w;
    const int b  = bt >> 11;
    const float* qb = g_qkv + (size_t)bt * W3;
    const float* km = g_kmean + b * WID;
    float s = 0.f;
    #pragma unroll 8
    for (int i = 0; i < 32; i++) {
        const int j = lane + 32 * i;
        const int h = j >> 6, c = j & 63;
        s += qb[h * 192 + c] * km[j];
    }
    #pragma unroll
    for (int msk = 16; msk; msk >>= 1) s += __shfl_xor_sync(0xffffffffu, s, msk);
    if (lane == 0) g_pos[bt] = s * 0.125f;
}

// ---------------------------------------------------------------------------
// aw — unchanged
// ---------------------------------------------------------------------------
__global__ __launch_bounds__(256) void aw_kernel()
{
    const int b = blockIdx.x;
    const int tid = threadIdx.x;
    float vals[8];
    float mn = 1e30f, mx = -1e30f;
    #pragma unroll
    for (int k = 0; k < 8; k++) {
        float v = g_pos[b * T_SEQ + tid + 256 * k];
        vals[k] = v;
        mn = fminf(mn, v);
        mx = fmaxf(mx, v);
    }
    __shared__ float smn[256], smx[256];
    smn[tid] = mn; smx[tid] = mx;
    __syncthreads();
    for (int s = 128; s; s >>= 1) {
        if (tid < s) {
            smn[tid] = fminf(smn[tid], smn[tid + s]);
            smx[tid] = fmaxf(smx[tid], smx[tid + s]);
        }
        __syncthreads();
    }
    const float gmn = smn[0];
    const float inv = 1.f / (smx[0] - smn[0] + 1e-6f);
    #pragma unroll
    for (int k = 0; k < 8; k++)
        g_aw[b * T_SEQ + tid + 256 * k] = (vals[k] - gmn) * inv;
}

// ---------------------------------------------------------------------------
// Flash attention — single fp16, m16n8k16, P in registers.
// NEW vs R14: Q fragments hoisted into registers (loaded once, 16 u32/warp)
// — deletes 16 LDS + addressing per 64-key chunk per warp.
// 256-key staging (validated R14). Smem 92160 B. 2 CTAs/SM.
// ---------------------------------------------------------------------------
static constexpr int FQS = 36;   // Q/K u32 row stride
static constexpr int FVS = 72;   // V u32 row stride
static constexpr int U_QH = 0;
static constexpr int KBUF = 64 * FQS;           // 2304 u32 per K buf
static constexpr int VBUF = 32 * FVS;           // 2304 u32 per V buf
static constexpr int U_K0 = 128 * FQS;          // 4608
static constexpr int U_V0 = U_K0 + 4 * KBUF;    // 13824
static constexpr int FA_TOT = (U_V0 + 4 * VBUF) * 4;  // 92160 bytes

__global__ __launch_bounds__(256, 2) void flash_attn_tc()
{
    extern __shared__ uint32_t smu[];
    uint32_t* QH = smu + U_QH;

    const int tid = threadIdx.x;
    const int wid = tid >> 5;
    const int lane = tid & 31;
    const int gid = lane >> 2, tig = lane & 3;
    const int bh  = blockIdx.y;
    const int b = bh >> 4, h = bh & 15;
    const int q0 = blockIdx.x * 128;
    const float* base = g_qkv + (size_t)b * T_SEQ * W3 + h * 192;

    // ---- Load Q tile (128 rows): prescale 1/8, single fp16, pack pairs ----
    {
        const int r = tid >> 1, c0 = (tid & 1) * 32;
        const float* qrow = base + (size_t)(q0 + r) * W3 + c0;
        #pragma unroll
        for (int i = 0; i < 8; i++) {
            float4 v = *(const float4*)(qrow + i * 4);
            const int w = r * FQS + c0 / 2 + i * 2;
            QH[w]     = fpack2(v.x * 0.125f, v.y * 0.125f);
            QH[w + 1] = fpack2(v.z * 0.125f, v.w * 0.125f);
        }
    }
    __syncthreads();

    const int wq = wid * 16;   // warp's q-row offset within tile

    // ---- hoist Q fragments for this warp's 16 rows into registers ----
    uint32_t qf[4][4];
    #pragma unroll
    for (int ks = 0; ks < 4; ks++)
        frag_au(qf[ks], QH, FQS, wq, ks * 8, gid, tig);

    float m0 = -1e30f, m1 = -1e30f, l0v = 0.f, l1v = 0.f;
    float O[8][4];
    #pragma unroll
    for (int j = 0; j < 8; j++)
        #pragma unroll
        for (int q = 0; q < 4; q++) O[j][q] = 0.f;

    // 64-key compute block (S -> online softmax -> PV), identical math.
    auto chunk = [&](const uint32_t* KH, const uint32_t* VH) {
        float s[8][4];
        #pragma unroll
        for (int j = 0; j < 8; j++)
            #pragma unroll
            for (int q = 0; q < 4; q++) s[j][q] = 0.f;
        #pragma unroll
        for (int ks = 0; ks < 4; ks++) {          // 4 x k16 over 64 channels
            #pragma unroll
            for (int j = 0; j < 8; j++) {
                const int krow = (j * 8 + gid) * FQS + ks * 8 + tig;
                uint32_t bh_[2];
                bh_[0] = KH[krow]; bh_[1] = KH[krow + 4];
                mma_f16(s[j], qf[ks], bh_);
            }
        }

        float mx0 = -1e30f, mx1 = -1e30f;
        #pragma unroll
        for (int j = 0; j < 8; j++) {
            mx0 = fmaxf(mx0, fmaxf(s[j][0], s[j][1]));
            mx1 = fmaxf(mx1, fmaxf(s[j][2], s[j][3]));
        }
        #pragma unroll
        for (int msk = 1; msk < 4; msk <<= 1) {
            mx0 = fmaxf(mx0, __shfl_xor_sync(0xffffffffu, mx0, msk));
            mx1 = fmaxf(mx1, __shfl_xor_sync(0xffffffffu, mx1, msk));
        }
        const float mn0 = fmaxf(m0, mx0), mn1 = fmaxf(m1, mx1);
        const float al0 = __expf(m0 - mn0), al1 = __expf(m1 - mn1);
        m0 = mn0; m1 = mn1;
        float sum0 = 0.f, sum1 = 0.f;
        #pragma unroll
        for (int j = 0; j < 8; j++) {
            s[j][0] = __expf(s[j][0] - mn0); sum0 += s[j][0];
            s[j][1] = __expf(s[j][1] - mn0); sum0 += s[j][1];
            s[j][2] = __expf(s[j][2] - mn1); sum1 += s[j][2];
            s[j][3] = __expf(s[j][3] - mn1); sum1 += s[j][3];
        }
        #pragma unroll
        for (int msk = 1; msk < 4; msk <<= 1) {
            sum0 += __shfl_xor_sync(0xffffffffu, sum0, msk);
            sum1 += __shfl_xor_sync(0xffffffffu, sum1, msk);
        }
        l0v = l0v * al0 + sum0;
        l1v = l1v * al1 + sum1;
        #pragma unroll
        for (int j = 0; j < 8; j++) {
            O[j][0] *= al0; O[j][1] *= al0;
            O[j][2] *= al1; O[j][3] *= al1;
        }

        #pragma unroll
        for (int kt = 0; kt < 4; kt++) {
            uint32_t ph[4];
            ph[0] = fpack2(s[2 * kt][0],     s[2 * kt][1]);
            ph[1] = fpack2(s[2 * kt][2],     s[2 * kt][3]);
            ph[2] = fpack2(s[2 * kt + 1][0], s[2 * kt + 1][1]);
            ph[3] = fpack2(s[2 * kt + 1][2], s[2 * kt + 1][3]);
            #pragma unroll
            for (int j = 0; j < 8; j++) {
                const int vrow = (kt * 8 + tig) * FVS + j * 8 + gid;
                uint32_t vh_[2];
                vh_[0] = VH[vrow]; vh_[1] = VH[vrow + 4 * FVS];
                mma_f16(O[j], ph, vh_);
            }
        }
    };

    for (int t0 = 0; t0 < T_SEQ; t0 += 256) {
        __syncthreads();   // all warps done with previous K/V buffers
        // ---- stage K for 4 x 64-key sub-chunks ----
        {
            const int r = tid >> 2, c0 = (tid & 3) * 16;
            #pragma unroll
            for (int half = 0; half < 4; half++) {
                const float* kr = base + (size_t)(t0 + half * 64 + r) * W3
                                  + CH + c0;
                uint32_t* KH = smu + U_K0 + half * KBUF;
                #pragma unroll
                for (int i = 0; i < 4; i++) {
                    float4 v = *(const float4*)(kr + i * 4);
                    const int w = r * FQS + c0 / 2 + i * 2;
                    KH[w]     = fpack2(v.x, v.y);
                    KH[w + 1] = fpack2(v.z, v.w);
                }
            }
        }
        // ---- stage V for 4 sub-chunks: word = (V[2kp][c], V[2kp+1][c]) ----
        {
            const int kp = tid >> 3, c0 = (tid & 7) * 8;
            #pragma unroll
            for (int half = 0; half < 4; half++) {
                const float* v0 = base + (size_t)(t0 + half * 64 + 2 * kp) * W3
                                  + 2 * CH + c0;
                const float* v1 = v0 + W3;
                float4 a0 = *(const float4*)(v0);
                float4 a1 = *(const float4*)(v0 + 4);
                float4 b0 = *(const float4*)(v1);
                float4 b1 = *(const float4*)(v1 + 4);
                const float va[8] = {a0.x, a0.y, a0.z, a0.w,
                                     a1.x, a1.y, a1.z, a1.w};
                const float vb[8] = {b0.x, b0.y, b0.z, b0.w,
                                     b1.x, b1.y, b1.z, b1.w};
                uint32_t* VH = smu + U_V0 + half * VBUF;
                #pragma unroll
                for (int c = 0; c < 8; c++)
                    VH[kp * FVS + c0 + c] = fpack2(va[c], vb[c]);
            }
        }
        __syncthreads();

        #pragma unroll
        for (int half = 0; half < 4; half++)
            chunk(smu + U_K0 + half * KBUF, smu + U_V0 + half * VBUF);
    }

    // ---- epilogue: normalize, apply adaptive weight, write g_attn ----
    const int t0r = q0 + wq + gid;
    const int t1r = t0r + 8;
    const float w0 = g_aw[b * T_SEQ + t0r] / l0v;
    const float w1 = g_aw[b * T_SEQ + t1r] / l1v;
    float* o0 = g_attn + (size_t)(b * T_SEQ + t0r) * WID + h * CH;
    float* o1 = g_attn + (size_t)(b * T_SEQ + t1r) * WID + h * CH;
    #pragma unroll
    for (int j = 0; j < 8; j++) {
        const int cc = j * 8 + 2 * tig;
        *(float2*)(o0 + cc) = make_float2(O[j][0] * w0, O[j][1] * w0);
        *(float2*)(o1 + cc) = make_float2(O[j][2] * w1, O[j][3] * w1);
    }
}

// ---------------------------------------------------------------------------
extern "C" void kernel_launch(void* const* d_in, const int* in_sizes, int n_in,
                              void* d_out, int out_size)
{
    const float* x     = (const float*)d_in[0];
    const float* Wqkv  = (const float*)d_in[1];
    const float* bqkv  = (const float*)d_in[2];
    const float* Wproj = (const float*)d_in[3];
    const float* bproj = (const float*)d_in[4];
    float* out = (float*)d_out;

    float *qkv, *attn;
    cudaGetSymbolAddress((void**)&qkv,  g_qkv);
    cudaGetSymbolAddress((void**)&attn, g_attn);

    static bool attr_set = false;
    if (!attr_set) {
        cudaFuncSetAttribute(gemm_f16, cudaFuncAttributeMaxDynamicSharedMemorySize, G_TOT);
        cudaFuncSetAttribute(flash_attn_tc, cudaFuncAttributeMaxDynamicSharedMemorySize, FA_TOT);
        attr_set = true;
    }

    // 1) qkv = x @ W_qkv + b_qkv       (tensor, single fp16, K-chunk 64)
    gemm_f16<<<dim3(W3 / 128, MROWS / 128), 256, G_TOT>>>(x, Wqkv, bqkv, qkv, W3, WID);
    // 2) k_mean  (1024-thread blocks)
    kmean_kernel<<<BATCH * HEADS, 1024>>>();
    // 3) pos = (q . k_mean)/8  (warp per row)
    pos_kernel<<<MROWS / 8, 256>>>();
    // 4) adaptive weight
    aw_kernel<<<BATCH, 256>>>();
    // 5) attention (tensor, fp16, Q frags in regs, 256-key staging; applies aw)
    flash_attn_tc<<<dim3(T_SEQ / 128, BH_N), 256, FA_TOT>>>();
    // 6) out = attn @ W_proj + b_proj  (tensor, single fp16, K-chunk 64)
    gemm_f16<<<dim3(WID / 128, MROWS / 128), 256, G_TOT>>>(attn, Wproj, bproj, out, WID, WID);
}

// round 16
// speedup vs baseline: 1.8892x; 1.0277x over previous
#include <cuda_runtime.h>
#include <cuda_fp16.h>
#include <cstdint>

// Problem constants
#define BATCH  2
#define T_SEQ  2048
#define WID    1024
#define HEADS  16
#define CH     64
#define W3     3072
#define MROWS  (BATCH * T_SEQ)   // 4096
#define BH_N   (BATCH * HEADS)   // 32

// Scratch (allocation-free rule: use __device__ globals)
__device__ float g_qkv [BATCH * T_SEQ * W3];    // 48 MB
__device__ float g_attn[BATCH * T_SEQ * WID];   // 16 MB
__device__ float g_kmean[BATCH * HEADS * CH];
__device__ float g_pos [BATCH * T_SEQ];
__device__ float g_aw  [BATCH * T_SEQ];

// Pre-converted fp16 K/V for flash (written once by convert_kv):
// K16: [bh][t][32 u32]   (channel-pair words)
// V16: [bh][t/2][64 u32] (key-pair words per channel)
#define KV_WORDS ((size_t)BH_N * T_SEQ * 32)   // 2M u32 = 8 MB each
__device__ uint32_t g_K16[KV_WORDS];
__device__ uint32_t g_V16[KV_WORDS];

// ---------------------------------------------------------------------------
// mma.sync helpers (plain PTX — legal in compute_103 PTX)
// ---------------------------------------------------------------------------
__device__ __forceinline__ void mma_f16(float* c, const uint32_t* a, const uint32_t* b)
{
    asm volatile(
        "mma.sync.aligned.m16n8k16.row.col.f32.f16.f16.f32 "
        "{%0,%1,%2,%3}, {%4,%5,%6,%7}, {%8,%9}, {%0,%1,%2,%3};"
        : "+f"(c[0]), "+f"(c[1]), "+f"(c[2]), "+f"(c[3])
        : "r"(a[0]), "r"(a[1]), "r"(a[2]), "r"(a[3]),
          "r"(b[0]), "r"(b[1]));
}

// Pack two fp32 into one fp16x2 word (low half = first value).
__device__ __forceinline__ uint32_t fpack2(float x0, float x1)
{
    uint32_t r;
    asm("cvt.rn.f16x2.f32 %0, %1, %2;" : "=r"(r) : "f"(x1), "f"(x0));
    return r;
}

// u32-packed A-frag (m16k16). lane = gid*4+tig; kw = k-word offset (k/2).
__device__ __forceinline__ void frag_au(uint32_t* a, const uint32_t* S, int SA,
                                        int r, int kw, int gid, int tig)
{
    const uint32_t* p0 = S + (r + gid) * SA + kw + tig;
    const uint32_t* p1 = S + (r + gid + 8) * SA + kw + tig;
    a[0] = p0[0]; a[1] = p1[0]; a[2] = p0[4]; a[3] = p1[4];
}

// ---------------------------------------------------------------------------
// Tensor-core GEMM, single fp16 product: C = A16 @ B16 + bias.
// K-chunk 64 (validated R14). Smem 37888 B.
// ---------------------------------------------------------------------------
static constexpr int BA_S = 20;    // A u32 row stride (16 words + pad)
static constexpr int BB_S = 136;   // B u32 kp-row stride (128 words + pad)
static constexpr int GA_SZ = 128 * BA_S;              // 2560 u32 per A buf
static constexpr int GB_SZ = 16 * BB_S;               // 2176 u32 per B buf
static constexpr int GB_B0 = 2 * GA_SZ;               // 5120
static constexpr int G_TOT = (GB_B0 + 2 * GB_SZ) * 4; // 37888 bytes

__global__ __launch_bounds__(256) void gemm_f16(
    const float* __restrict__ A, const float* __restrict__ B,
    const float* __restrict__ bias, float* __restrict__ C,
    int N, int K)
{
    extern __shared__ uint32_t smu[];

    const int tid = threadIdx.x;
    const int wid = tid >> 5;
    const int lane = tid & 31;
    const int gid = lane >> 2, tig = lane & 3;
    const int wm = (wid >> 1) * 32;   // warp row offset in tile
    const int wn = (wid & 1) * 64;    // warp col offset in tile
    const int row0 = blockIdx.y * 128;
    const int col0 = blockIdx.x * 128;

    // stagers
    const int ar  = tid >> 1;           // 0..127
    const int ak  = (tid & 1) * 16;     // float offset 0 or 16
    const int bkp = tid >> 4;           // 0..15 (k-pair row)
    const int bn0 = (tid & 15) * 8;     // 0..120

    const float* Ap  = A + (size_t)(row0 + ar) * K + ak;
    const float* Bp0 = B + col0 + bn0;

    float c[2][8][4];
    #pragma unroll
    for (int i = 0; i < 2; i++)
        #pragma unroll
        for (int j = 0; j < 8; j++)
            #pragma unroll
            for (int q = 0; q < 4; q++) c[i][j][q] = 0.f;

    for (int kc = 0; kc < K; kc += 64) {
        __syncthreads();
        // ---- stage A: two 32-wide sub-chunks ----
        #pragma unroll
        for (int sb = 0; sb < 2; sb++) {
            uint32_t* AH = smu + sb * GA_SZ;
            #pragma unroll
            for (int i = 0; i < 4; i++) {
                float4 v = *(const float4*)(Ap + kc + sb * 32 + i * 4);
                const int w = ar * BA_S + ak / 2 + i * 2;
                AH[w]     = fpack2(v.x, v.y);
                AH[w + 1] = fpack2(v.z, v.w);
            }
        }
        // ---- stage B: two 32-wide sub-chunks ----
        #pragma unroll
        for (int sb = 0; sb < 2; sb++) {
            uint32_t* BH = smu + GB_B0 + sb * GB_SZ;
            const float* Bp = Bp0 + (size_t)(kc + sb * 32 + 2 * bkp) * N;
            float4 x0 = *(const float4*)(Bp);
            float4 x1 = *(const float4*)(Bp + 4);
            float4 y0 = *(const float4*)(Bp + N);
            float4 y1 = *(const float4*)(Bp + N + 4);
            const float xa[8] = {x0.x, x0.y, x0.z, x0.w, x1.x, x1.y, x1.z, x1.w};
            const float ya[8] = {y0.x, y0.y, y0.z, y0.w, y1.x, y1.y, y1.z, y1.w};
            #pragma unroll
            for (int cI = 0; cI < 8; cI++)     // word = (B[k][n], B[k+1][n])
                BH[bkp * BB_S + bn0 + cI] = fpack2(xa[cI], ya[cI]);
        }
        __syncthreads();

        // ---- MMA: 2 sub-chunks x 2 k16 steps, single product ----
        #pragma unroll
        for (int sb = 0; sb < 2; sb++) {
            const uint32_t* AH = smu + sb * GA_SZ;
            const uint32_t* BH = smu + GB_B0 + sb * GB_SZ;
            #pragma unroll
            for (int ks = 0; ks < 2; ks++) {
                uint32_t ah[2][4];
                frag_au(ah[0], AH, BA_S, wm,      ks * 8, gid, tig);
                frag_au(ah[1], AH, BA_S, wm + 16, ks * 8, gid, tig);
                #pragma unroll
                for (int j = 0; j < 8; j++) {
                    const int base = (ks * 8 + tig) * BB_S + wn + j * 8 + gid;
                    uint32_t bh[2];
                    bh[0] = BH[base]; bh[1] = BH[base + 4 * BB_S];
                    mma_f16(c[0][j], ah[0], bh);
                    mma_f16(c[1][j], ah[1], bh);
                }
            }
        }
    }

    // ---- epilogue: c frags + bias -> gmem ----
    #pragma unroll
    for (int i = 0; i < 2; i++) {
        const int r0 = row0 + wm + i * 16 + gid;
        #pragma unroll
        for (int j = 0; j < 8; j++) {
            const int col = col0 + wn + j * 8 + 2 * tig;
            float2 bv = *(const float2*)&bias[col];
            float2 o0 = make_float2(c[i][j][0] + bv.x, c[i][j][1] + bv.y);
            float2 o1 = make_float2(c[i][j][2] + bv.x, c[i][j][3] + bv.y);
            *(float2*)&C[(size_t)r0 * N + col]       = o0;
            *(float2*)&C[(size_t)(r0 + 8) * N + col] = o1;
        }
    }
}

// ---------------------------------------------------------------------------
// convert_kv: fp32 K,V slices of g_qkv -> packed fp16 arrays in EXACTLY the
// layouts flash stages into smem (identical fpack2 rounding, done once
// instead of 16x per head). grid = (T/64, BH), 256 threads.
// ---------------------------------------------------------------------------
__global__ __launch_bounds__(256) void convert_kv()
{
    const int tid = threadIdx.x;
    const int bh  = blockIdx.y;
    const int b = bh >> 4, h = bh & 15;
    const int t0 = blockIdx.x * 64;
    const float* base = g_qkv + (size_t)b * T_SEQ * W3 + h * 192;

    // K: r = tid>>2 (0..63), c0 = (tid&3)*16
    {
        const int r = tid >> 2, c0 = (tid & 3) * 16;
        const float* krow = base + (size_t)(t0 + r) * W3 + CH + c0;
        const size_t g = ((size_t)bh * T_SEQ + t0 + r) * 32 + c0 / 2;
        #pragma unroll
        for (int i = 0; i < 4; i++) {
            float4 v = *(const float4*)(krow + i * 4);
            g_K16[g + i * 2]     = fpack2(v.x, v.y);
            g_K16[g + i * 2 + 1] = fpack2(v.z, v.w);
        }
    }
    // V: kp = tid>>3 (0..31), c0 = (tid&7)*8; word = (V[2kp][c], V[2kp+1][c])
    {
        const int kp = tid >> 3, c0 = (tid & 7) * 8;
        const float* v0 = base + (size_t)(t0 + 2 * kp) * W3 + 2 * CH + c0;
        const float* v1 = v0 + W3;
        float4 a0 = *(const float4*)(v0);
        float4 a1 = *(const float4*)(v0 + 4);
        float4 b0 = *(const float4*)(v1);
        float4 b1 = *(const float4*)(v1 + 4);
        const float va[8] = {a0.x, a0.y, a0.z, a0.w, a1.x, a1.y, a1.z, a1.w};
        const float vb[8] = {b0.x, b0.y, b0.z, b0.w, b1.x, b1.y, b1.z, b1.w};
        const size_t g = ((size_t)bh * (T_SEQ / 2) + t0 / 2 + kp) * 64 + c0;
        #pragma unroll
        for (int c = 0; c < 8; c++)
            g_V16[g + c] = fpack2(va[c], vb[c]);
    }
}

// ---------------------------------------------------------------------------
// k_mean — 1024 threads (validated R13)
// ---------------------------------------------------------------------------
__global__ __launch_bounds__(1024) void kmean_kernel()
{
    const int bh = blockIdx.x;
    const int b = bh >> 4, h = bh & 15;
    const int c  = threadIdx.x & 63;
    const int tg = threadIdx.x >> 6;   // 0..15
    const float* base = g_qkv + (size_t)b * T_SEQ * W3 + h * 192 + CH + c;
    float s = 0.f;
    for (int t = tg; t < T_SEQ; t += 16) s += base[(size_t)t * W3];
    __shared__ float red[16][64];
    red[tg][c] = s;
    __syncthreads();
    if (tg == 0) {
        float tot = 0.f;
        #pragma unroll
        for (int w = 0; w < 16; w++) tot += red[w][c];
        g_kmean[bh * CH + c] = tot * (1.f / (float)T_SEQ);
    }
}

// ---------------------------------------------------------------------------
// pos — one warp per row (validated R13)
// ---------------------------------------------------------------------------
__global__ __launch_bounds__(256) void pos_kernel()
{
    const int w = threadIdx.x >> 5, lane = threadIdx.x & 31;
    const int bt = blockIdx.x * 8 + w;
    const int b  = bt >> 11;
    const float* qb = g_qkv + (size_t)bt * W3;
    const float* km = g_kmean + b * WID;
    float s = 0.f;
    #pragma unroll 8
    for (int i = 0; i < 32; i++) {
        const int j = lane + 32 * i;
        const int h = j >> 6, c = j & 63;
        s += qb[h * 192 + c] * km[j];
    }
    #pragma unroll
    for (int msk = 16; msk; msk >>= 1) s += __shfl_xor_sync(0xffffffffu, s, msk);
    if (lane == 0) g_pos[bt] = s * 0.125f;
}

// ---------------------------------------------------------------------------
// aw — unchanged
// ---------------------------------------------------------------------------
__global__ __launch_bounds__(256) void aw_kernel()
{
    const int b = blockIdx.x;
    const int tid = threadIdx.x;
    float vals[8];
    float mn = 1e30f, mx = -1e30f;
    #pragma unroll
    for (int k = 0; k < 8; k++) {
        float v = g_pos[b * T_SEQ + tid + 256 * k];
        vals[k] = v;
        mn = fminf(mn, v);
        mx = fmaxf(mx, v);
    }
    __shared__ float smn[256], smx[256];
    smn[tid] = mn; smx[tid] = mx;
    __syncthreads();
    for (int s = 128; s; s >>= 1) {
        if (tid < s) {
            smn[tid] = fminf(smn[tid], smn[tid + s]);
            smx[tid] = fmaxf(smx[tid], smx[tid + s]);
        }
        __syncthreads();
    }
    const float gmn = smn[0];
    const float inv = 1.f / (smx[0] - smn[0] + 1e-6f);
    #pragma unroll
    for (int k = 0; k < 8; k++)
        g_aw[b * T_SEQ + tid + 256 * k] = (vals[k] - gmn) * inv;
}

// ---------------------------------------------------------------------------
// Flash attention — single fp16, m16n8k16, Q frags in regs, P in regs.
// NEW vs R15: K/V staging is pure uint4 copies from pre-converted g_K16/g_V16
// (half the gmem bytes, zero conversion ALU in the hot loop).
// 256-key staging. Smem 92160 B. 2 CTAs/SM.
// ---------------------------------------------------------------------------
static constexpr int FQS = 36;   // Q/K u32 row stride
static constexpr int FVS = 72;   // V u32 row stride
static constexpr int U_QH = 0;
static constexpr int KBUF = 64 * FQS;           // 2304 u32 per K buf
static constexpr int VBUF = 32 * FVS;           // 2304 u32 per V buf
static constexpr int U_K0 = 128 * FQS;          // 4608
static constexpr int U_V0 = U_K0 + 4 * KBUF;    // 13824
static constexpr int FA_TOT = (U_V0 + 4 * VBUF) * 4;  // 92160 bytes

__global__ __launch_bounds__(256, 2) void flash_attn_tc()
{
    extern __shared__ uint32_t smu[];
    uint32_t* QH = smu + U_QH;

    const int tid = threadIdx.x;
    const int wid = tid >> 5;
    const int lane = tid & 31;
    const int gid = lane >> 2, tig = lane & 3;
    const int bh  = blockIdx.y;
    const int b = bh >> 4, h = bh & 15;
    const int q0 = blockIdx.x * 128;
    const float* base = g_qkv + (size_t)b * T_SEQ * W3 + h * 192;

    // ---- Load Q tile (128 rows): prescale 1/8, single fp16, pack pairs ----
    {
        const int r = tid >> 1, c0 = (tid & 1) * 32;
        const float* qrow = base + (size_t)(q0 + r) * W3 + c0;
        #pragma unroll
        for (int i = 0; i < 8; i++) {
            float4 v = *(const float4*)(qrow + i * 4);
            const int w = r * FQS + c0 / 2 + i * 2;
            QH[w]     = fpack2(v.x * 0.125f, v.y * 0.125f);
            QH[w + 1] = fpack2(v.z * 0.125f, v.w * 0.125f);
        }
    }
    __syncthreads();

    const int wq = wid * 16;   // warp's q-row offset within tile

    // ---- hoist Q fragments for this warp's 16 rows into registers ----
    uint32_t qf[4][4];
    #pragma unroll
    for (int ks = 0; ks < 4; ks++)
        frag_au(qf[ks], QH, FQS, wq, ks * 8, gid, tig);

    float m0 = -1e30f, m1 = -1e30f, l0v = 0.f, l1v = 0.f;
    float O[8][4];
    #pragma unroll
    for (int j = 0; j < 8; j++)
        #pragma unroll
        for (int q = 0; q < 4; q++) O[j][q] = 0.f;

    // 64-key compute block (S -> online softmax -> PV), identical math.
    auto chunk = [&](const uint32_t* KH, const uint32_t* VH) {
        float s[8][4];
        #pragma unroll
        for (int j = 0; j < 8; j++)
            #pragma unroll
            for (int q = 0; q < 4; q++) s[j][q] = 0.f;
        #pragma unroll
        for (int ks = 0; ks < 4; ks++) {          // 4 x k16 over 64 channels
            #pragma unroll
            for (int j = 0; j < 8; j++) {
                const int krow = (j * 8 + gid) * FQS + ks * 8 + tig;
                uint32_t bh_[2];
                bh_[0] = KH[krow]; bh_[1] = KH[krow + 4];
                mma_f16(s[j], qf[ks], bh_);
            }
        }

        float mx0 = -1e30f, mx1 = -1e30f;
        #pragma unroll
        for (int j = 0; j < 8; j++) {
            mx0 = fmaxf(mx0, fmaxf(s[j][0], s[j][1]));
            mx1 = fmaxf(mx1, fmaxf(s[j][2], s[j][3]));
        }
        #pragma unroll
        for (int msk = 1; msk < 4; msk <<= 1) {
            mx0 = fmaxf(mx0, __shfl_xor_sync(0xffffffffu, mx0, msk));
            mx1 = fmaxf(mx1, __shfl_xor_sync(0xffffffffu, mx1, msk));
        }
        const float mn0 = fmaxf(m0, mx0), mn1 = fmaxf(m1, mx1);
        const float al0 = __expf(m0 - mn0), al1 = __expf(m1 - mn1);
        m0 = mn0; m1 = mn1;
        float sum0 = 0.f, sum1 = 0.f;
        #pragma unroll
        for (int j = 0; j < 8; j++) {
            s[j][0] = __expf(s[j][0] - mn0); sum0 += s[j][0];
            s[j][1] = __expf(s[j][1] - mn0); sum0 += s[j][1];
            s[j][2] = __expf(s[j][2] - mn1); sum1 += s[j][2];
            s[j][3] = __expf(s[j][3] - mn1); sum1 += s[j][3];
        }
        #pragma unroll
        for (int msk = 1; msk < 4; msk <<= 1) {
            sum0 += __shfl_xor_sync(0xffffffffu, sum0, msk);
            sum1 += __shfl_xor_sync(0xffffffffu, sum1, msk);
        }
        l0v = l0v * al0 + sum0;
        l1v = l1v * al1 + sum1;
        #pragma unroll
        for (int j = 0; j < 8; j++) {
            O[j][0] *= al0; O[j][1] *= al0;
            O[j][2] *= al1; O[j][3] *= al1;
        }

        #pragma unroll
        for (int kt = 0; kt < 4; kt++) {
            uint32_t ph[4];
            ph[0] = fpack2(s[2 * kt][0],     s[2 * kt][1]);
            ph[1] = fpack2(s[2 * kt][2],     s[2 * kt][3]);
            ph[2] = fpack2(s[2 * kt + 1][0], s[2 * kt + 1][1]);
            ph[3] = fpack2(s[2 * kt + 1][2], s[2 * kt + 1][3]);
            #pragma unroll
            for (int j = 0; j < 8; j++) {
                const int vrow = (kt * 8 + tig) * FVS + j * 8 + gid;
                uint32_t vh_[2];
                vh_[0] = VH[vrow]; vh_[1] = VH[vrow + 4 * FVS];
                mma_f16(O[j], ph, vh_);
            }
        }
    };

    for (int t0 = 0; t0 < T_SEQ; t0 += 256) {
        __syncthreads();   // all warps done with previous K/V buffers
        // ---- stage K for 4 x 64-key sub-chunks: pure uint4 copies ----
        {
            const int r = tid >> 2, w0 = (tid & 3) * 8;
            #pragma unroll
            for (int half = 0; half < 4; half++) {
                const size_t gk = ((size_t)bh * T_SEQ + t0 + half * 64 + r) * 32 + w0;
                uint32_t* KH = smu + U_K0 + half * KBUF;
                uint4 a = *(const uint4*)(g_K16 + gk);
                uint4 c = *(const uint4*)(g_K16 + gk + 4);
                *(uint4*)(KH + r * FQS + w0)     = a;
                *(uint4*)(KH + r * FQS + w0 + 4) = c;
            }
        }
        // ---- stage V for 4 sub-chunks: pure uint4 copies ----
        {
            const int kp = tid >> 3, c0 = (tid & 7) * 8;
            #pragma unroll
            for (int half = 0; half < 4; half++) {
                const size_t gv = ((size_t)bh * (T_SEQ / 2)
                                   + (t0 + half * 64) / 2 + kp) * 64 + c0;
                uint32_t* VH = smu + U_V0 + half * VBUF;
                uint4 a = *(const uint4*)(g_V16 + gv);
                uint4 c = *(const uint4*)(g_V16 + gv + 4);
                *(uint4*)(VH + kp * FVS + c0)     = a;
                *(uint4*)(VH + kp * FVS + c0 + 4) = c;
            }
        }
        __syncthreads();

        #pragma unroll
        for (int half = 0; half < 4; half++)
            chunk(smu + U_K0 + half * KBUF, smu + U_V0 + half * VBUF);
    }

    // ---- epilogue: normalize, apply adaptive weight, write g_attn ----
    const int t0r = q0 + wq + gid;
    const int t1r = t0r + 8;
    const float w0 = g_aw[b * T_SEQ + t0r] / l0v;
    const float w1 = g_aw[b * T_SEQ + t1r] / l1v;
    float* o0 = g_attn + (size_t)(b * T_SEQ + t0r) * WID + h * CH;
    float* o1 = g_attn + (size_t)(b * T_SEQ + t1r) * WID + h * CH;
    #pragma unroll
    for (int j = 0; j < 8; j++) {
        const int cc = j * 8 + 2 * tig;
        *(float2*)(o0 + cc) = make_float2(O[j][0] * w0, O[j][1] * w0);
        *(float2*)(o1 + cc) = make_float2(O[j][2] * w1, O[j][3] * w1);
    }
}

// ---------------------------------------------------------------------------
extern "C" void kernel_launch(void* const* d_in, const int* in_sizes, int n_in,
                              void* d_out, int out_size)
{
    const float* x     = (const float*)d_in[0];
    const float* Wqkv  = (const float*)d_in[1];
    const float* bqkv  = (const float*)d_in[2];
    const float* Wproj = (const float*)d_in[3];
    const float* bproj = (const float*)d_in[4];
    float* out = (float*)d_out;

    float *qkv, *attn;
    cudaGetSymbolAddress((void**)&qkv,  g_qkv);
    cudaGetSymbolAddress((void**)&attn, g_attn);

    static bool attr_set = false;
    if (!attr_set) {
        cudaFuncSetAttribute(gemm_f16, cudaFuncAttributeMaxDynamicSharedMemorySize, G_TOT);
        cudaFuncSetAttribute(flash_attn_tc, cudaFuncAttributeMaxDynamicSharedMemorySize, FA_TOT);
        attr_set = true;
    }

    // 1) qkv = x @ W_qkv + b_qkv       (tensor, single fp16, K-chunk 64)
    gemm_f16<<<dim3(W3 / 128, MROWS / 128), 256, G_TOT>>>(x, Wqkv, bqkv, qkv, W3, WID);
    // 2) pre-convert K/V to fp16 flash layouts (once, not 16x per head)
    convert_kv<<<dim3(T_SEQ / 64, BH_N), 256>>>();
    // 3) k_mean  (1024-thread blocks)
    kmean_kernel<<<BATCH * HEADS, 1024>>>();
    // 4) pos = (q . k_mean)/8  (warp per row)
    pos_kernel<<<MROWS / 8, 256>>>();
    // 5) adaptive weight
    aw_kernel<<<BATCH, 256>>>();
    // 6) attention (tensor, fp16, copy-only K/V staging; applies aw)
    flash_attn_tc<<<dim3(T_SEQ / 128, BH_N), 256, FA_TOT>>>();
    // 7) out = attn @ W_proj + b_proj  (tensor, single fp16, K-chunk 64)
    gemm_f16<<<dim3(WID / 128, MROWS / 128), 256, G_TOT>>>(attn, Wproj, bproj, out, WID, WID);
}

// round 17
// speedup vs baseline: 1.8906x; 1.0007x over previous
#include <cuda_runtime.h>
#include <cuda_fp16.h>
#include <cstdint>

// Problem constants
#define BATCH  2
#define T_SEQ  2048
#define WID    1024
#define HEADS  16
#define CH     64
#define W3     3072
#define MROWS  (BATCH * T_SEQ)   // 4096
#define BH_N   (BATCH * HEADS)   // 32

// Scratch (allocation-free rule: use __device__ globals)
__device__ float g_qkv [BATCH * T_SEQ * W3];    // 48 MB
__device__ float g_attn[BATCH * T_SEQ * WID];   // 16 MB
__device__ float g_kmean[BATCH * HEADS * CH];
__device__ float g_pos [BATCH * T_SEQ];
__device__ unsigned g_mmx[BATCH * 2];   // [b*2]=min key, [b*2+1]=max key

// Pre-converted fp16 K/V for flash (written once by convert_kv):
// K16: [bh][t][32 u32]   (channel-pair words)
// V16: [bh][t/2][64 u32] (key-pair words per channel)
#define KV_WORDS ((size_t)BH_N * T_SEQ * 32)   // 2M u32 = 8 MB each
__device__ uint32_t g_K16[KV_WORDS];
__device__ uint32_t g_V16[KV_WORDS];

// Monotonic uint encoding of float (order-preserving).
__device__ __forceinline__ unsigned fkey(float f)
{
    unsigned u = __float_as_uint(f);
    return (u & 0x80000000u) ? ~u : (u | 0x80000000u);
}
__device__ __forceinline__ float funkey(unsigned k)
{
    unsigned u = (k & 0x80000000u) ? (k ^ 0x80000000u) : ~k;
    return __uint_as_float(u);
}

// ---------------------------------------------------------------------------
// mma.sync helpers (plain PTX — legal in compute_103 PTX)
// ---------------------------------------------------------------------------
__device__ __forceinline__ void mma_f16(float* c, const uint32_t* a, const uint32_t* b)
{
    asm volatile(
        "mma.sync.aligned.m16n8k16.row.col.f32.f16.f16.f32 "
        "{%0,%1,%2,%3}, {%4,%5,%6,%7}, {%8,%9}, {%0,%1,%2,%3};"
        : "+f"(c[0]), "+f"(c[1]), "+f"(c[2]), "+f"(c[3])
        : "r"(a[0]), "r"(a[1]), "r"(a[2]), "r"(a[3]),
          "r"(b[0]), "r"(b[1]));
}

// Pack two fp32 into one fp16x2 word (low half = first value).
__device__ __forceinline__ uint32_t fpack2(float x0, float x1)
{
    uint32_t r;
    asm("cvt.rn.f16x2.f32 %0, %1, %2;" : "=r"(r) : "f"(x1), "f"(x0));
    return r;
}

// u32-packed A-frag (m16k16). lane = gid*4+tig; kw = k-word offset (k/2).
__device__ __forceinline__ void frag_au(uint32_t* a, const uint32_t* S, int SA,
                                        int r, int kw, int gid, int tig)
{
    const uint32_t* p0 = S + (r + gid) * SA + kw + tig;
    const uint32_t* p1 = S + (r + gid + 8) * SA + kw + tig;
    a[0] = p0[0]; a[1] = p1[0]; a[2] = p0[4]; a[3] = p1[4];
}

// ---------------------------------------------------------------------------
// Tensor-core GEMM, single fp16 product: C = A16 @ B16 + bias.
// K-chunk 64 (validated R14). Smem 37888 B.
// ---------------------------------------------------------------------------
static constexpr int BA_S = 20;    // A u32 row stride (16 words + pad)
static constexpr int BB_S = 136;   // B u32 kp-row stride (128 words + pad)
static constexpr int GA_SZ = 128 * BA_S;              // 2560 u32 per A buf
static constexpr int GB_SZ = 16 * BB_S;               // 2176 u32 per B buf
static constexpr int GB_B0 = 2 * GA_SZ;               // 5120
static constexpr int G_TOT = (GB_B0 + 2 * GB_SZ) * 4; // 37888 bytes

__global__ __launch_bounds__(256) void gemm_f16(
    const float* __restrict__ A, const float* __restrict__ B,
    const float* __restrict__ bias, float* __restrict__ C,
    int N, int K)
{
    extern __shared__ uint32_t smu[];

    const int tid = threadIdx.x;
    const int wid = tid >> 5;
    const int lane = tid & 31;
    const int gid = lane >> 2, tig = lane & 3;
    const int wm = (wid >> 1) * 32;   // warp row offset in tile
    const int wn = (wid & 1) * 64;    // warp col offset in tile
    const int row0 = blockIdx.y * 128;
    const int col0 = blockIdx.x * 128;

    // stagers
    const int ar  = tid >> 1;           // 0..127
    const int ak  = (tid & 1) * 16;     // float offset 0 or 16
    const int bkp = tid >> 4;           // 0..15 (k-pair row)
    const int bn0 = (tid & 15) * 8;     // 0..120

    const float* Ap  = A + (size_t)(row0 + ar) * K + ak;
    const float* Bp0 = B + col0 + bn0;

    float c[2][8][4];
    #pragma unroll
    for (int i = 0; i < 2; i++)
        #pragma unroll
        for (int j = 0; j < 8; j++)
            #pragma unroll
            for (int q = 0; q < 4; q++) c[i][j][q] = 0.f;

    for (int kc = 0; kc < K; kc += 64) {
        __syncthreads();
        // ---- stage A: two 32-wide sub-chunks ----
        #pragma unroll
        for (int sb = 0; sb < 2; sb++) {
            uint32_t* AH = smu + sb * GA_SZ;
            #pragma unroll
            for (int i = 0; i < 4; i++) {
                float4 v = *(const float4*)(Ap + kc + sb * 32 + i * 4);
                const int w = ar * BA_S + ak / 2 + i * 2;
                AH[w]     = fpack2(v.x, v.y);
                AH[w + 1] = fpack2(v.z, v.w);
            }
        }
        // ---- stage B: two 32-wide sub-chunks ----
        #pragma unroll
        for (int sb = 0; sb < 2; sb++) {
            uint32_t* BH = smu + GB_B0 + sb * GB_SZ;
            const float* Bp = Bp0 + (size_t)(kc + sb * 32 + 2 * bkp) * N;
            float4 x0 = *(const float4*)(Bp);
            float4 x1 = *(const float4*)(Bp + 4);
            float4 y0 = *(const float4*)(Bp + N);
            float4 y1 = *(const float4*)(Bp + N + 4);
            const float xa[8] = {x0.x, x0.y, x0.z, x0.w, x1.x, x1.y, x1.z, x1.w};
            const float ya[8] = {y0.x, y0.y, y0.z, y0.w, y1.x, y1.y, y1.z, y1.w};
            #pragma unroll
            for (int cI = 0; cI < 8; cI++)     // word = (B[k][n], B[k+1][n])
                BH[bkp * BB_S + bn0 + cI] = fpack2(xa[cI], ya[cI]);
        }
        __syncthreads();

        // ---- MMA: 2 sub-chunks x 2 k16 steps, single product ----
        #pragma unroll
        for (int sb = 0; sb < 2; sb++) {
            const uint32_t* AH = smu + sb * GA_SZ;
            const uint32_t* BH = smu + GB_B0 + sb * GB_SZ;
            #pragma unroll
            for (int ks = 0; ks < 2; ks++) {
                uint32_t ah[2][4];
                frag_au(ah[0], AH, BA_S, wm,      ks * 8, gid, tig);
                frag_au(ah[1], AH, BA_S, wm + 16, ks * 8, gid, tig);
                #pragma unroll
                for (int j = 0; j < 8; j++) {
                    const int base = (ks * 8 + tig) * BB_S + wn + j * 8 + gid;
                    uint32_t bh[2];
                    bh[0] = BH[base]; bh[1] = BH[base + 4 * BB_S];
                    mma_f16(c[0][j], ah[0], bh);
                    mma_f16(c[1][j], ah[1], bh);
                }
            }
        }
    }

    // ---- epilogue: c frags + bias -> gmem ----
    #pragma unroll
    for (int i = 0; i < 2; i++) {
        const int r0 = row0 + wm + i * 16 + gid;
        #pragma unroll
        for (int j = 0; j < 8; j++) {
            const int col = col0 + wn + j * 8 + 2 * tig;
            float2 bv = *(const float2*)&bias[col];
            float2 o0 = make_float2(c[i][j][0] + bv.x, c[i][j][1] + bv.y);
            float2 o1 = make_float2(c[i][j][2] + bv.x, c[i][j][3] + bv.y);
            *(float2*)&C[(size_t)r0 * N + col]       = o0;
            *(float2*)&C[(size_t)(r0 + 8) * N + col] = o1;
        }
    }
}

// ---------------------------------------------------------------------------
// convert_kv: fp32 K,V slices of g_qkv -> packed fp16 arrays in EXACTLY the
// layouts flash stages into smem. Also initializes the pos min/max sentinels
// (graph-replay safe: runs every launch). grid = (T/64, BH), 256 threads.
// ---------------------------------------------------------------------------
__global__ __launch_bounds__(256) void convert_kv()
{
    const int tid = threadIdx.x;
    const int bh  = blockIdx.y;
    const int b = bh >> 4, h = bh & 15;
    const int t0 = blockIdx.x * 64;
    const float* base = g_qkv + (size_t)b * T_SEQ * W3 + h * 192;

    if (blockIdx.x == 0 && blockIdx.y == 0 && tid < BATCH * 2)
        g_mmx[tid] = (tid & 1) ? 0u : 0xFFFFFFFFu;   // max slot 0, min slot ~0

    // K: r = tid>>2 (0..63), c0 = (tid&3)*16
    {
        const int r = tid >> 2, c0 = (tid & 3) * 16;
        const float* krow = base + (size_t)(t0 + r) * W3 + CH + c0;
        const size_t g = ((size_t)bh * T_SEQ + t0 + r) * 32 + c0 / 2;
        #pragma unroll
        for (int i = 0; i < 4; i++) {
            float4 v = *(const float4*)(krow + i * 4);
            g_K16[g + i * 2]     = fpack2(v.x, v.y);
            g_K16[g + i * 2 + 1] = fpack2(v.z, v.w);
        }
    }
    // V: kp = tid>>3 (0..31), c0 = (tid&7)*8; word = (V[2kp][c], V[2kp+1][c])
    {
        const int kp = tid >> 3, c0 = (tid & 7) * 8;
        const float* v0 = base + (size_t)(t0 + 2 * kp) * W3 + 2 * CH + c0;
        const float* v1 = v0 + W3;
        float4 a0 = *(const float4*)(v0);
        float4 a1 = *(const float4*)(v0 + 4);
        float4 b0 = *(const float4*)(v1);
        float4 b1 = *(const float4*)(v1 + 4);
        const float va[8] = {a0.x, a0.y, a0.z, a0.w, a1.x, a1.y, a1.z, a1.w};
        const float vb[8] = {b0.x, b0.y, b0.z, b0.w, b1.x, b1.y, b1.z, b1.w};
        const size_t g = ((size_t)bh * (T_SEQ / 2) + t0 / 2 + kp) * 64 + c0;
        #pragma unroll
        for (int c = 0; c < 8; c++)
            g_V16[g + c] = fpack2(va[c], vb[c]);
    }
}

// ---------------------------------------------------------------------------
// k_mean — 1024 threads (validated R13)
// ---------------------------------------------------------------------------
__global__ __launch_bounds__(1024) void kmean_kernel()
{
    const int bh = blockIdx.x;
    const int b = bh >> 4, h = bh & 15;
    const int c  = threadIdx.x & 63;
    const int tg = threadIdx.x >> 6;   // 0..15
    const float* base = g_qkv + (size_t)b * T_SEQ * W3 + h * 192 + CH + c;
    float s = 0.f;
    for (int t = tg; t < T_SEQ; t += 16) s += base[(size_t)t * W3];
    __shared__ float red[16][64];
    red[tg][c] = s;
    __syncthreads();
    if (tg == 0) {
        float tot = 0.f;
        #pragma unroll
        for (int w = 0; w < 16; w++) tot += red[w][c];
        g_kmean[bh * CH + c] = tot * (1.f / (float)T_SEQ);
    }
}

// ---------------------------------------------------------------------------
// pos — one warp per row, float4 loads, publishes per-batch min/max via
// monotonic-uint atomics (exact; order-independent). aw_kernel is deleted.
// ---------------------------------------------------------------------------
__global__ __launch_bounds__(256) void pos_kernel()
{
    const int w = threadIdx.x >> 5, lane = threadIdx.x & 31;
    const int bt = blockIdx.x * 8 + w;
    const int b  = bt >> 11;
    const float* qb = g_qkv + (size_t)bt * W3;
    const float* km = g_kmean + b * WID;
    float s = 0.f;
    #pragma unroll
    for (int i = 0; i < 8; i++) {
        const int h = 2 * i + (lane >> 4);
        const int c = (lane & 15) * 4;
        float4 qv = *(const float4*)(qb + h * 192 + c);
        float4 kv = *(const float4*)(km + h * 64 + c);
        s = fmaf(qv.x, kv.x, s);
        s = fmaf(qv.y, kv.y, s);
        s = fmaf(qv.z, kv.z, s);
        s = fmaf(qv.w, kv.w, s);
    }
    #pragma unroll
    for (int msk = 16; msk; msk >>= 1) s += __shfl_xor_sync(0xffffffffu, s, msk);
    if (lane == 0) {
        const float p = s * 0.125f;
        g_pos[bt] = p;
        const unsigned k = fkey(p);
        atomicMin(&g_mmx[b * 2],     k);
        atomicMax(&g_mmx[b * 2 + 1], k);
    }
}

// ---------------------------------------------------------------------------
// Flash attention — single fp16, m16n8k16, Q frags in regs, P in regs,
// copy-only K/V staging (validated R16). NEW: adaptive weight computed
// inline from g_pos + g_mmx (aw_kernel deleted).
// 256-key staging. Smem 92160 B. 2 CTAs/SM.
// ---------------------------------------------------------------------------
static constexpr int FQS = 36;   // Q/K u32 row stride
static constexpr int FVS = 72;   // V u32 row stride
static constexpr int U_QH = 0;
static constexpr int KBUF = 64 * FQS;           // 2304 u32 per K buf
static constexpr int VBUF = 32 * FVS;           // 2304 u32 per V buf
static constexpr int U_K0 = 128 * FQS;          // 4608
static constexpr int U_V0 = U_K0 + 4 * KBUF;    // 13824
static constexpr int FA_TOT = (U_V0 + 4 * VBUF) * 4;  // 92160 bytes

__global__ __launch_bounds__(256, 2) void flash_attn_tc()
{
    extern __shared__ uint32_t smu[];
    uint32_t* QH = smu + U_QH;

    const int tid = threadIdx.x;
    const int wid = tid >> 5;
    const int lane = tid & 31;
    const int gid = lane >> 2, tig = lane & 3;
    const int bh  = blockIdx.y;
    const int b = bh >> 4, h = bh & 15;
    const int q0 = blockIdx.x * 128;
    const float* base = g_qkv + (size_t)b * T_SEQ * W3 + h * 192;

    // ---- Load Q tile (128 rows): prescale 1/8, single fp16, pack pairs ----
    {
        const int r = tid >> 1, c0 = (tid & 1) * 32;
        const float* qrow = base + (size_t)(q0 + r) * W3 + c0;
        #pragma unroll
        for (int i = 0; i < 8; i++) {
            float4 v = *(const float4*)(qrow + i * 4);
            const int w = r * FQS + c0 / 2 + i * 2;
            QH[w]     = fpack2(v.x * 0.125f, v.y * 0.125f);
            QH[w + 1] = fpack2(v.z * 0.125f, v.w * 0.125f);
        }
    }
    __syncthreads();

    const int wq = wid * 16;   // warp's q-row offset within tile

    // ---- hoist Q fragments for this warp's 16 rows into registers ----
    uint32_t qf[4][4];
    #pragma unroll
    for (int ks = 0; ks < 4; ks++)
        frag_au(qf[ks], QH, FQS, wq, ks * 8, gid, tig);

    float m0 = -1e30f, m1 = -1e30f, l0v = 0.f, l1v = 0.f;
    float O[8][4];
    #pragma unroll
    for (int j = 0; j < 8; j++)
        #pragma unroll
        for (int q = 0; q < 4; q++) O[j][q] = 0.f;

    // 64-key compute block (S -> online softmax -> PV), identical math.
    auto chunk = [&](const uint32_t* KH, const uint32_t* VH) {
        float s[8][4];
        #pragma unroll
        for (int j = 0; j < 8; j++)
            #pragma unroll
            for (int q = 0; q < 4; q++) s[j][q] = 0.f;
        #pragma unroll
        for (int ks = 0; ks < 4; ks++) {          // 4 x k16 over 64 channels
            #pragma unroll
            for (int j = 0; j < 8; j++) {
                const int krow = (j * 8 + gid) * FQS + ks * 8 + tig;
                uint32_t bh_[2];
                bh_[0] = KH[krow]; bh_[1] = KH[krow + 4];
                mma_f16(s[j], qf[ks], bh_);
            }
        }

        float mx0 = -1e30f, mx1 = -1e30f;
        #pragma unroll
        for (int j = 0; j < 8; j++) {
            mx0 = fmaxf(mx0, fmaxf(s[j][0], s[j][1]));
            mx1 = fmaxf(mx1, fmaxf(s[j][2], s[j][3]));
        }
        #pragma unroll
        for (int msk = 1; msk < 4; msk <<= 1) {
            mx0 = fmaxf(mx0, __shfl_xor_sync(0xffffffffu, mx0, msk));
            mx1 = fmaxf(mx1, __shfl_xor_sync(0xffffffffu, mx1, msk));
        }
        const float mn0 = fmaxf(m0, mx0), mn1 = fmaxf(m1, mx1);
        const float al0 = __expf(m0 - mn0), al1 = __expf(m1 - mn1);
        m0 = mn0; m1 = mn1;
        float sum0 = 0.f, sum1 = 0.f;
        #pragma unroll
        for (int j = 0; j < 8; j++) {
            s[j][0] = __expf(s[j][0] - mn0); sum0 += s[j][0];
            s[j][1] = __expf(s[j][1] - mn0); sum0 += s[j][1];
            s[j][2] = __expf(s[j][2] - mn1); sum1 += s[j][2];
            s[j][3] = __expf(s[j][3] - mn1); sum1 += s[j][3];
        }
        #pragma unroll
        for (int msk = 1; msk < 4; msk <<= 1) {
            sum0 += __shfl_xor_sync(0xffffffffu, sum0, msk);
            sum1 += __shfl_xor_sync(0xffffffffu, sum1, msk);
        }
        l0v = l0v * al0 + sum0;
        l1v = l1v * al1 + sum1;
        #pragma unroll
        for (int j = 0; j < 8; j++) {
            O[j][0] *= al0; O[j][1] *= al0;
            O[j][2] *= al1; O[j][3] *= al1;
        }

        #pragma unroll
        for (int kt = 0; kt < 4; kt++) {
            uint32_t ph[4];
            ph[0] = fpack2(s[2 * kt][0],     s[2 * kt][1]);
            ph[1] = fpack2(s[2 * kt][2],     s[2 * kt][3]);
            ph[2] = fpack2(s[2 * kt + 1][0], s[2 * kt + 1][1]);
            ph[3] = fpack2(s[2 * kt + 1][2], s[2 * kt + 1][3]);
            #pragma unroll
            for (int j = 0; j < 8; j++) {
                const int vrow = (kt * 8 + tig) * FVS + j * 8 + gid;
                uint32_t vh_[2];
                vh_[0] = VH[vrow]; vh_[1] = VH[vrow + 4 * FVS];
                mma_f16(O[j], ph, vh_);
            }
        }
    };

    for (int t0 = 0; t0 < T_SEQ; t0 += 256) {
        __syncthreads();   // all warps done with previous K/V buffers
        // ---- stage K for 4 x 64-key sub-chunks: pure uint4 copies ----
        {
            const int r = tid >> 2, w0 = (tid & 3) * 8;
            #pragma unroll
            for (int half = 0; half < 4; half++) {
                const size_t gk = ((size_t)bh * T_SEQ + t0 + half * 64 + r) * 32 + w0;
                uint32_t* KH = smu + U_K0 + half * KBUF;
                uint4 a = *(const uint4*)(g_K16 + gk);
                uint4 c = *(const uint4*)(g_K16 + gk + 4);
                *(uint4*)(KH + r * FQS + w0)     = a;
                *(uint4*)(KH + r * FQS + w0 + 4) = c;
            }
        }
        // ---- stage V for 4 sub-chunks: pure uint4 copies ----
        {
            const int kp = tid >> 3, c0 = (tid & 7) * 8;
            #pragma unroll
            for (int half = 0; half < 4; half++) {
                const size_t gv = ((size_t)bh * (T_SEQ / 2)
                                   + (t0 + half * 64) / 2 + kp) * 64 + c0;
                uint32_t* VH = smu + U_V0 + half * VBUF;
                uint4 a = *(const uint4*)(g_V16 + gv);
                uint4 c = *(const uint4*)(g_V16 + gv + 4);
                *(uint4*)(VH + kp * FVS + c0)     = a;
                *(uint4*)(VH + kp * FVS + c0 + 4) = c;
            }
        }
        __syncthreads();

        #pragma unroll
        for (int half = 0; half < 4; half++)
            chunk(smu + U_K0 + half * KBUF, smu + U_V0 + half * VBUF);
    }

    // ---- epilogue: aw computed inline; normalize; write g_attn ----
    const float mn  = funkey(g_mmx[b * 2]);
    const float mx  = funkey(g_mmx[b * 2 + 1]);
    const float inv = 1.f / (mx - mn + 1e-6f);
    const int t0r = q0 + wq + gid;
    const int t1r = t0r + 8;
    const float w0 = (g_pos[b * T_SEQ + t0r] - mn) * inv / l0v;
    const float w1 = (g_pos[b * T_SEQ + t1r] - mn) * inv / l1v;
    float* o0 = g_attn + (size_t)(b * T_SEQ + t0r) * WID + h * CH;
    float* o1 = g_attn + (size_t)(b * T_SEQ + t1r) * WID + h * CH;
    #pragma unroll
    for (int j = 0; j < 8; j++) {
        const int cc = j * 8 + 2 * tig;
        *(float2*)(o0 + cc) = make_float2(O[j][0] * w0, O[j][1] * w0);
        *(float2*)(o1 + cc) = make_float2(O[j][2] * w1, O[j][3] * w1);
    }
}

// ---------------------------------------------------------------------------
extern "C" void kernel_launch(void* const* d_in, const int* in_sizes, int n_in,
                              void* d_out, int out_size)
{
    const float* x     = (const float*)d_in[0];
    const float* Wqkv  = (const float*)d_in[1];
    const float* bqkv  = (const float*)d_in[2];
    const float* Wproj = (const float*)d_in[3];
    const float* bproj = (const float*)d_in[4];
    float* out = (float*)d_out;

    float *qkv, *attn;
    cudaGetSymbolAddress((void**)&qkv,  g_qkv);
    cudaGetSymbolAddress((void**)&attn, g_attn);

    static bool attr_set = false;
    if (!attr_set) {
        cudaFuncSetAttribute(gemm_f16, cudaFuncAttributeMaxDynamicSharedMemorySize, G_TOT);
        cudaFuncSetAttribute(flash_attn_tc, cudaFuncAttributeMaxDynamicSharedMemorySize, FA_TOT);
        attr_set = true;
    }

    // 1) qkv = x @ W_qkv + b_qkv       (tensor, single fp16, K-chunk 64)
    gemm_f16<<<dim3(W3 / 128, MROWS / 128), 256, G_TOT>>>(x, Wqkv, bqkv, qkv, W3, WID);
    // 2) pre-convert K/V to fp16 flash layouts + init min/max sentinels
    convert_kv<<<dim3(T_SEQ / 64, BH_N), 256>>>();
    // 3) k_mean  (1024-thread blocks)
    kmean_kernel<<<BATCH * HEADS, 1024>>>();
    // 4) pos = (q . k_mean)/8  (warp/row, float4, atomic min/max publish)
    pos_kernel<<<MROWS / 8, 256>>>();
    // 5) attention (tensor, fp16; aw computed inline in epilogue)
    flash_attn_tc<<<dim3(T_SEQ / 128, BH_N), 256, FA_TOT>>>();
    // 6) out = attn @ W_proj + b_proj  (tensor, single fp16, K-chunk 64)
    gemm_f16<<<dim3(WID / 128, MROWS / 128), 256, G_TOT>>>(attn, Wproj, bproj, out, WID, WID);
}